// round 5
// baseline (speedup 1.0000x reference)
#include <cuda_runtime.h>

#define N_NODES 100000
#define N_EDGES 800000
#define N_LABEL 400000
#define CH      256
#define H1      128
#define H2      32

// Scratch (module-load allocated; allowed per harness rules)
__device__ __align__(16) float g_xw[(size_t)N_NODES * CH];
__device__ __align__(16) float g_h[(size_t)N_NODES * CH];
__device__ float g_deg[N_NODES];
__device__ float g_dis[N_NODES];

// ---------------------------------------------------------------------------
// xw = x @ W_gcn   (100000x256 @ 256x256), 64x64 tile, 16 k-step, 4x4/thread
// ---------------------------------------------------------------------------
__global__ void gemm_xw(const float* __restrict__ X, const float* __restrict__ W) {
    __shared__ float As[64][17];
    __shared__ float Bs[16][68];
    const int tid = threadIdx.x;
    const int tx = tid & 15, ty = tid >> 4;
    const int row0 = blockIdx.y * 64, col0 = blockIdx.x * 64;

    float acc[4][4] = {};

    for (int k0 = 0; k0 < CH; k0 += 16) {
        int ar = tid >> 2;
        int ac = (tid & 3) * 4;
        int grow = row0 + ar;
        float4 av = make_float4(0.f, 0.f, 0.f, 0.f);
        if (grow < N_NODES)
            av = *(const float4*)&X[(size_t)grow * CH + k0 + ac];
        As[ar][ac] = av.x; As[ar][ac + 1] = av.y;
        As[ar][ac + 2] = av.z; As[ar][ac + 3] = av.w;
        int bk = tid >> 4, bn = (tid & 15) * 4;
        float4 bv = *(const float4*)&W[(size_t)(k0 + bk) * CH + col0 + bn];
        Bs[bk][bn] = bv.x; Bs[bk][bn + 1] = bv.y;
        Bs[bk][bn + 2] = bv.z; Bs[bk][bn + 3] = bv.w;
        __syncthreads();

        #pragma unroll
        for (int k = 0; k < 16; k++) {
            float a[4], b[4];
            #pragma unroll
            for (int i = 0; i < 4; i++) a[i] = As[ty * 4 + i][k];
            #pragma unroll
            for (int j = 0; j < 4; j++) b[j] = Bs[k][tx * 4 + j];
            #pragma unroll
            for (int i = 0; i < 4; i++)
                #pragma unroll
                for (int j = 0; j < 4; j++)
                    acc[i][j] += a[i] * b[j];
        }
        __syncthreads();
    }

    #pragma unroll
    for (int i = 0; i < 4; i++) {
        int row = row0 + ty * 4 + i;
        if (row < N_NODES) {
            float4 v = make_float4(acc[i][0], acc[i][1], acc[i][2], acc[i][3]);
            *(float4*)&g_xw[(size_t)row * CH + col0 + tx * 4] = v;
        }
    }
}

// ---------------------------------------------------------------------------
// Degree / normalization (indices int32)
// ---------------------------------------------------------------------------
__global__ void deg_init() {
    int i = blockIdx.x * blockDim.x + threadIdx.x;
    if (i < N_NODES) g_deg[i] = 1.0f;  // self-loop pre-count
}

__global__ void deg_edges(const int* __restrict__ ei) {
    int e = blockIdx.x * blockDim.x + threadIdx.x;
    if (e >= N_EDGES) return;
    int d = ei[N_EDGES + e];
    if ((unsigned)d < N_NODES) atomicAdd(&g_deg[d], 1.0f);
}

__global__ void compute_dis() {
    int i = blockIdx.x * blockDim.x + threadIdx.x;
    if (i < N_NODES) g_dis[i] = rsqrtf(g_deg[i]);
}

// h = b_gcn + xw * dis^2   (self-loop term + bias)
__global__ void h_init(const float* __restrict__ b_gcn) {
    int idx = blockIdx.x * blockDim.x + threadIdx.x;  // over N_NODES*64 float4s
    if (idx >= N_NODES * (CH / 4)) return;
    int i = idx >> 6;
    int c4 = idx & 63;
    float s = g_dis[i]; s *= s;
    float4 xv = ((const float4*)g_xw)[idx];
    float4 bv = ((const float4*)b_gcn)[c4];
    ((float4*)g_h)[idx] = make_float4(bv.x + xv.x * s, bv.y + xv.y * s,
                                      bv.z + xv.z * s, bv.w + xv.w * s);
}

// ---------------------------------------------------------------------------
// Edge scatter: h[dst] += xw[src] * dis[src]*dis[dst]   (warp per edge)
// ---------------------------------------------------------------------------
__global__ void scatter_edges(const int* __restrict__ ei) {
    int e = blockIdx.x * 8 + (threadIdx.x >> 5);
    if (e >= N_EDGES) return;
    int lane = threadIdx.x & 31;
    int src = ei[e];
    int dst = ei[N_EDGES + e];
    if ((unsigned)src >= N_NODES || (unsigned)dst >= N_NODES) return;
    float coef = g_dis[src] * g_dis[dst];
    const float4* xs = (const float4*)&g_xw[(size_t)src * CH];
    float* hd = &g_h[(size_t)dst * CH];
    #pragma unroll
    for (int m = 0; m < 2; m++) {
        int c4 = lane + m * 32;
        float4 v = xs[c4];
        atomicAdd(&hd[c4 * 4 + 0], v.x * coef);
        atomicAdd(&hd[c4 * 4 + 1], v.y * coef);
        atomicAdd(&hd[c4 * 4 + 2], v.z * coef);
        atomicAdd(&hd[c4 * 4 + 3], v.w * coef);
    }
}

// ---------------------------------------------------------------------------
// Fused MLP: one block = 48 label edges (fits 48KB static smem with a
// NON-OVERLAPPING sO layout — stride exactly 32 f4; the round-3/4 bug was
// SO stride 30 f4 < 32 f4 row length => cross-warp write race).
// Phase A: k-chunks of 32; sD[48] stride 9 f4 + sW1[32] stride 33 f4.
// Phase B: smem reused as sO[48] stride 32 f4 + sW2T[32] stride 33 f4.
// ---------------------------------------------------------------------------
#define TILE_E   48
#define SD_F4    (TILE_E * 9)            // 432 f4
#define SW1_F4   (32 * 33)               // 1056 f4
#define SO_F4    (TILE_E * 32)           // 1536 f4
#define SW2T_OFF (TILE_E * 32 * 4)       // float offset 6144
#define UNION_F  (SW2T_OFF + 32 * 132)   // 10368 floats = 41472 B

__global__ void __launch_bounds__(256)
mlp_kernel(const int* __restrict__ eli,
           const float* __restrict__ W1, const float* __restrict__ b1,
           const float* __restrict__ W2, const float* __restrict__ b2,
           const float* __restrict__ W3, const float* __restrict__ b3,
           float* __restrict__ out) {
    __shared__ __align__(16) float sm[UNION_F];
    __shared__ int sIdx[2 * TILE_E];

    const int tid  = threadIdx.x;
    const int tx   = tid & 15, ty = tid >> 4;
    const int lane = tid & 31;
    const int tile0 = blockIdx.x * TILE_E;

    float b1r[8];
    #pragma unroll
    for (int j = 0; j < 8; j++) b1r[j] = b1[tx * 8 + j];
    const float b2r = b2[lane];
    const float w3r = W3[lane];
    const float b3r = b3[0];

    if (tid < TILE_E) {
        int gi = tile0 + tid;
        int v = (gi < N_LABEL) ? eli[gi] : 0;
        sIdx[tid] = ((unsigned)v < N_NODES) ? v : 0;
    } else if (tid < 2 * TILE_E) {
        int gi = tile0 + tid - TILE_E;
        int v = (gi < N_LABEL) ? eli[N_LABEL + gi] : 0;
        sIdx[tid] = ((unsigned)v < N_NODES) ? v : 0;
    }
    __syncthreads();

    float acc[3][8];
    #pragma unroll
    for (int i = 0; i < 3; i++)
        #pragma unroll
        for (int j = 0; j < 8; j++) acc[i][j] = b1r[j];

    float4* sD4  = (float4*)sm;            // [48] rows, stride 9 f4
    float4* sW14 = (float4*)sm + SD_F4;    // [32] rows, stride 33 f4
    const float4* h4 = (const float4*)g_h;
    const float4* W1g4 = (const float4*)W1;

    for (int k0 = 0; k0 < CH; k0 += 32) {
        // stage D chunk: 48 edges x 8 f4 = 384 f4
        #pragma unroll
        for (int it = 0; it < 2; it++) {
            int idx = tid + 256 * it;
            if (idx < TILE_E * 8) {
                int e = idx >> 3, c4 = idx & 7;
                int a = sIdx[e], b = sIdx[TILE_E + e];
                float4 va = h4[(size_t)a * 64 + (k0 >> 2) + c4];
                float4 vb = h4[(size_t)b * 64 + (k0 >> 2) + c4];
                sD4[e * 9 + c4] = make_float4(vb.x - va.x, vb.y - va.y,
                                              vb.z - va.z, vb.w - va.w);
            }
        }
        // stage W1 chunk: rows k0..k0+31, 128 cols = 1024 f4
        #pragma unroll
        for (int it = 0; it < 4; it++) {
            int idx = tid + 256 * it;
            int k = idx >> 5, c4 = idx & 31;
            sW14[k * 33 + c4] = W1g4[(size_t)(k0 + k) * 32 + c4];
        }
        __syncthreads();

        #pragma unroll
        for (int k4 = 0; k4 < 8; k4++) {
            float4 a4[3];
            #pragma unroll
            for (int i = 0; i < 3; i++) a4[i] = sD4[(ty * 3 + i) * 9 + k4];
            #pragma unroll
            for (int kk = 0; kk < 4; kk++) {
                int k = k4 * 4 + kk;
                float4 bv0 = sW14[k * 33 + tx * 2];
                float4 bv1 = sW14[k * 33 + tx * 2 + 1];
                #pragma unroll
                for (int i = 0; i < 3; i++) {
                    float av = (kk == 0) ? a4[i].x : (kk == 1) ? a4[i].y
                             : (kk == 2) ? a4[i].z : a4[i].w;
                    acc[i][0] += av * bv0.x; acc[i][1] += av * bv0.y;
                    acc[i][2] += av * bv0.z; acc[i][3] += av * bv0.w;
                    acc[i][4] += av * bv1.x; acc[i][5] += av * bv1.y;
                    acc[i][6] += av * bv1.z; acc[i][7] += av * bv1.w;
                }
            }
        }
        __syncthreads();   // before restaging smem
    }

    // Phase B: relu(acc) -> sO (stride 32 f4, NO overlap), stage W2^T, L2+L3
    float4* sO4  = (float4*)sm;            // [48] rows, stride 32 f4
    float*  sW2t = sm + SW2T_OFF;          // [32] rows, stride 132 floats
    const float4* sW2t4 = (const float4*)sW2t;

    #pragma unroll
    for (int i = 0; i < 3; i++) {
        int e = ty * 3 + i;
        sO4[e * 32 + tx * 2] = make_float4(fmaxf(acc[i][0], 0.f), fmaxf(acc[i][1], 0.f),
                                           fmaxf(acc[i][2], 0.f), fmaxf(acc[i][3], 0.f));
        sO4[e * 32 + tx * 2 + 1] = make_float4(fmaxf(acc[i][4], 0.f), fmaxf(acc[i][5], 0.f),
                                               fmaxf(acc[i][6], 0.f), fmaxf(acc[i][7], 0.f));
    }
    // W2 [128][32] -> sW2t [j2][k], coalesced read + transposed store
    #pragma unroll
    for (int it = 0; it < 16; it++) {
        int idx = tid + 256 * it;
        int k = idx >> 5, j2 = idx & 31;
        sW2t[j2 * 132 + k] = W2[idx];
    }
    __syncthreads();

    #pragma unroll
    for (int i = 0; i < 6; i++) {
        int e = (tid >> 5) + 8 * i;        // warp-uniform edge, lane = j2
        float acc2 = b2r;
        #pragma unroll
        for (int k4 = 0; k4 < 32; k4++) {
            float4 ov = sO4[e * 32 + k4];
            float4 wv = sW2t4[lane * 33 + k4];
            acc2 += ov.x * wv.x + ov.y * wv.y + ov.z * wv.z + ov.w * wv.w;
        }
        float v = fmaxf(acc2, 0.f) * w3r;
        #pragma unroll
        for (int off = 16; off; off >>= 1)
            v += __shfl_xor_sync(0xffffffffu, v, off);
        if (lane == 0 && tile0 + e < N_LABEL) out[tile0 + e] = v + b3r;
    }
}

// ---------------------------------------------------------------------------
// Host: resolve inputs BY ELEMENT COUNT (robust to metadata.txt ordering).
// ---------------------------------------------------------------------------
extern "C" void kernel_launch(void* const* d_in, const int* in_sizes, int n_in,
                              void* d_out, int out_size) {
    const float *x = 0, *W_gcn = 0, *b_gcn = 0, *W1 = 0, *b1 = 0, *W2 = 0,
                *b2 = 0, *W3 = 0, *b3 = 0;
    const int *ei = 0, *eli = 0;
    int idx32[2] = {-1, -1};
    int n32 = 0, i128 = -1;

    for (int i = 0; i < n_in; i++) {
        switch (in_sizes[i]) {
            case 25600000: x     = (const float*)d_in[i]; break;
            case 1600000:  ei    = (const int*)d_in[i];   break;
            case 800000:   eli   = (const int*)d_in[i];   break;
            case 65536:    W_gcn = (const float*)d_in[i]; break;
            case 32768:    W1    = (const float*)d_in[i]; break;
            case 4096:     W2    = (const float*)d_in[i]; break;
            case 256:      b_gcn = (const float*)d_in[i]; break;
            case 128:      b1    = (const float*)d_in[i]; i128 = i; break;
            case 32:       if (n32 < 2) idx32[n32] = i; n32++; break;
            case 1:        b3    = (const float*)d_in[i]; break;
            default: break;
        }
    }
    if (n32 >= 2) {
        if (idx32[0] < i128) {          // a 32-tensor before b1 => it's W3
            W3 = (const float*)d_in[idx32[0]];
            b2 = (const float*)d_in[idx32[1]];
        } else {                         // dict order: b2 then W3
            b2 = (const float*)d_in[idx32[0]];
            W3 = (const float*)d_in[idx32[1]];
        }
    }
    if (!x)     x     = (const float*)d_in[0];
    if (!ei)    ei    = (const int*)d_in[1];
    if (!eli)   eli   = (const int*)d_in[2];
    if (!W_gcn) W_gcn = (const float*)d_in[3];
    if (!b_gcn) b_gcn = (const float*)d_in[4];
    if (!W1)    W1    = (const float*)d_in[5];
    if (!b1)    b1    = (const float*)d_in[6];
    if (!W2)    W2    = (const float*)d_in[7];
    if (!b2)    b2    = (const float*)d_in[8];
    if (!W3)    W3    = (const float*)d_in[9];
    if (!b3)    b3    = (const float*)d_in[10];
    float* out = (float*)d_out;

    dim3 ggrid(CH / 64, (N_NODES + 63) / 64);
    gemm_xw<<<ggrid, 256>>>(x, W_gcn);

    deg_init<<<(N_NODES + 255) / 256, 256>>>();
    deg_edges<<<(N_EDGES + 255) / 256, 256>>>(ei);
    compute_dis<<<(N_NODES + 255) / 256, 256>>>();
    h_init<<<(N_NODES * (CH / 4) + 255) / 256, 256>>>(b_gcn);
    scatter_edges<<<(N_EDGES + 7) / 8, 256>>>(ei);

    mlp_kernel<<<(N_LABEL + TILE_E - 1) / TILE_E, 256>>>(eli, W1, b1, W2, b2,
                                                         W3, b3, out);
}

// round 6
// speedup vs baseline: 1.1838x; 1.1838x over previous
#include <cuda_runtime.h>

#define N_NODES 100000
#define N_EDGES 800000
#define N_LABEL 400000
#define CH      256
#define H1      128
#define H2      32

#define SCAN_CHUNK 512
#define NBLK_SCAN  ((N_NODES + SCAN_CHUNK - 1) / SCAN_CHUNK)   // 196

// Scratch (module-load allocated; allowed per harness rules)
__device__ __align__(16) float g_xw[(size_t)N_NODES * CH];
__device__ __align__(16) float g_h[(size_t)N_NODES * CH];
__device__ float g_dis[N_NODES];
__device__ int   g_cnt[N_NODES];
__device__ int   g_rowptr[N_NODES + 1];
__device__ int   g_cursor[N_NODES];
__device__ int   g_csrc[N_EDGES];
__device__ int   g_partial[NBLK_SCAN];
__device__ int   g_poff[NBLK_SCAN];

// ---------------------------------------------------------------------------
// xw = x @ W_gcn   (100000x256 @ 256x256), 64x64 tile, 16 k-step, 4x4/thread
// ---------------------------------------------------------------------------
__global__ void gemm_xw(const float* __restrict__ X, const float* __restrict__ W) {
    __shared__ float As[64][17];
    __shared__ float Bs[16][68];
    const int tid = threadIdx.x;
    const int tx = tid & 15, ty = tid >> 4;
    const int row0 = blockIdx.y * 64, col0 = blockIdx.x * 64;

    float acc[4][4] = {};

    for (int k0 = 0; k0 < CH; k0 += 16) {
        int ar = tid >> 2;
        int ac = (tid & 3) * 4;
        int grow = row0 + ar;
        float4 av = make_float4(0.f, 0.f, 0.f, 0.f);
        if (grow < N_NODES)
            av = *(const float4*)&X[(size_t)grow * CH + k0 + ac];
        As[ar][ac] = av.x; As[ar][ac + 1] = av.y;
        As[ar][ac + 2] = av.z; As[ar][ac + 3] = av.w;
        int bk = tid >> 4, bn = (tid & 15) * 4;
        float4 bv = *(const float4*)&W[(size_t)(k0 + bk) * CH + col0 + bn];
        Bs[bk][bn] = bv.x; Bs[bk][bn + 1] = bv.y;
        Bs[bk][bn + 2] = bv.z; Bs[bk][bn + 3] = bv.w;
        __syncthreads();

        #pragma unroll
        for (int k = 0; k < 16; k++) {
            float a[4], b[4];
            #pragma unroll
            for (int i = 0; i < 4; i++) a[i] = As[ty * 4 + i][k];
            #pragma unroll
            for (int j = 0; j < 4; j++) b[j] = Bs[k][tx * 4 + j];
            #pragma unroll
            for (int i = 0; i < 4; i++)
                #pragma unroll
                for (int j = 0; j < 4; j++)
                    acc[i][j] += a[i] * b[j];
        }
        __syncthreads();
    }

    #pragma unroll
    for (int i = 0; i < 4; i++) {
        int row = row0 + ty * 4 + i;
        if (row < N_NODES) {
            float4 v = make_float4(acc[i][0], acc[i][1], acc[i][2], acc[i][3]);
            *(float4*)&g_xw[(size_t)row * CH + col0 + tx * 4] = v;
        }
    }
}

// ---------------------------------------------------------------------------
// CSR build: histogram -> 3-pass exclusive scan -> bucket fill
// ---------------------------------------------------------------------------
__global__ void zero_cnt() {
    int i = blockIdx.x * blockDim.x + threadIdx.x;
    if (i < N_NODES) g_cnt[i] = 0;
}

__global__ void hist(const int* __restrict__ ei) {
    int e = blockIdx.x * blockDim.x + threadIdx.x;
    if (e >= N_EDGES) return;
    int d = ei[N_EDGES + e];
    if ((unsigned)d < N_NODES) atomicAdd(&g_cnt[d], 1);
}

// block sums of 512-element chunks
__global__ void __launch_bounds__(SCAN_CHUNK) scan1() {
    __shared__ int s[SCAN_CHUNK];
    int tid = threadIdx.x;
    int i = blockIdx.x * SCAN_CHUNK + tid;
    s[tid] = (i < N_NODES) ? g_cnt[i] : 0;
    __syncthreads();
    #pragma unroll
    for (int off = SCAN_CHUNK / 2; off > 0; off >>= 1) {
        if (tid < off) s[tid] += s[tid + off];
        __syncthreads();
    }
    if (tid == 0) g_partial[blockIdx.x] = s[0];
}

// single-block scan of the 196 partials (exclusive offsets)
__global__ void __launch_bounds__(256) scan2() {
    __shared__ int s[256];
    int tid = threadIdx.x;
    int v = (tid < NBLK_SCAN) ? g_partial[tid] : 0;
    s[tid] = v;
    __syncthreads();
    #pragma unroll
    for (int off = 1; off < 256; off <<= 1) {
        int t = (tid >= off) ? s[tid - off] : 0;
        __syncthreads();
        s[tid] += t;
        __syncthreads();
    }
    if (tid < NBLK_SCAN) g_poff[tid] = s[tid] - v;            // exclusive
    if (tid == NBLK_SCAN - 1) g_rowptr[N_NODES] = s[tid];     // total valid edges
}

// per-chunk exclusive scan -> rowptr + cursor; also dis = rsqrt(cnt+1)
__global__ void __launch_bounds__(SCAN_CHUNK) scan3() {
    __shared__ int s[SCAN_CHUNK];
    int tid = threadIdx.x;
    int i = blockIdx.x * SCAN_CHUNK + tid;
    int c = (i < N_NODES) ? g_cnt[i] : 0;
    s[tid] = c;
    __syncthreads();
    #pragma unroll
    for (int off = 1; off < SCAN_CHUNK; off <<= 1) {
        int t = (tid >= off) ? s[tid - off] : 0;
        __syncthreads();
        s[tid] += t;
        __syncthreads();
    }
    if (i < N_NODES) {
        int excl = g_poff[blockIdx.x] + s[tid] - c;
        g_rowptr[i] = excl;
        g_cursor[i] = excl;
        g_dis[i] = rsqrtf((float)(c + 1));    // +1 self-loop
    }
}

__global__ void fill(const int* __restrict__ ei) {
    int e = blockIdx.x * blockDim.x + threadIdx.x;
    if (e >= N_EDGES) return;
    int src = ei[e];
    int dst = ei[N_EDGES + e];
    if ((unsigned)src >= N_NODES || (unsigned)dst >= N_NODES) return;
    int p = atomicAdd(&g_cursor[dst], 1);
    g_csrc[p] = src;
}

// ---------------------------------------------------------------------------
// Gather (replaces atomic scatter + h_init): warp per node.
// h[i] = b + dis[i] * ( dis[i]*xw[i] + sum_{s in in(i)} dis[s]*xw[s] )
// ---------------------------------------------------------------------------
__global__ void __launch_bounds__(256) gather(const float* __restrict__ b_gcn) {
    int node = blockIdx.x * 8 + (threadIdx.x >> 5);
    if (node >= N_NODES) return;
    int lane = threadIdx.x & 31;
    const float4* xw4 = (const float4*)g_xw;
    const float4* b4  = (const float4*)b_gcn;

    float di = g_dis[node];
    float4 v0 = xw4[(size_t)node * 64 + lane];
    float4 v1 = xw4[(size_t)node * 64 + 32 + lane];
    float4 acc0 = make_float4(di * v0.x, di * v0.y, di * v0.z, di * v0.w);
    float4 acc1 = make_float4(di * v1.x, di * v1.y, di * v1.z, di * v1.w);

    int beg = g_rowptr[node], end = g_rowptr[node + 1];
    for (int j = beg; j < end; j++) {
        int s = g_csrc[j];                       // warp-uniform broadcast load
        float c = g_dis[s];
        float4 w0 = xw4[(size_t)s * 64 + lane];
        float4 w1 = xw4[(size_t)s * 64 + 32 + lane];
        acc0.x += c * w0.x; acc0.y += c * w0.y;
        acc0.z += c * w0.z; acc0.w += c * w0.w;
        acc1.x += c * w1.x; acc1.y += c * w1.y;
        acc1.z += c * w1.z; acc1.w += c * w1.w;
    }

    float4 bv0 = b4[lane], bv1 = b4[lane + 32];
    float4* h4 = (float4*)g_h;
    h4[(size_t)node * 64 + lane] =
        make_float4(bv0.x + di * acc0.x, bv0.y + di * acc0.y,
                    bv0.z + di * acc0.z, bv0.w + di * acc0.w);
    h4[(size_t)node * 64 + 32 + lane] =
        make_float4(bv1.x + di * acc1.x, bv1.y + di * acc1.y,
                    bv1.z + di * acc1.z, bv1.w + di * acc1.w);
}

// ---------------------------------------------------------------------------
// Fused MLP: one block = 48 label edges (unchanged from round-5 PASS).
// ---------------------------------------------------------------------------
#define TILE_E   48
#define SD_F4    (TILE_E * 9)
#define SW2T_OFF (TILE_E * 32 * 4)
#define UNION_F  (SW2T_OFF + 32 * 132)

__global__ void __launch_bounds__(256)
mlp_kernel(const int* __restrict__ eli,
           const float* __restrict__ W1, const float* __restrict__ b1,
           const float* __restrict__ W2, const float* __restrict__ b2,
           const float* __restrict__ W3, const float* __restrict__ b3,
           float* __restrict__ out) {
    __shared__ __align__(16) float sm[UNION_F];
    __shared__ int sIdx[2 * TILE_E];

    const int tid  = threadIdx.x;
    const int tx   = tid & 15, ty = tid >> 4;
    const int lane = tid & 31;
    const int tile0 = blockIdx.x * TILE_E;

    float b1r[8];
    #pragma unroll
    for (int j = 0; j < 8; j++) b1r[j] = b1[tx * 8 + j];
    const float b2r = b2[lane];
    const float w3r = W3[lane];
    const float b3r = b3[0];

    if (tid < TILE_E) {
        int gi = tile0 + tid;
        int v = (gi < N_LABEL) ? eli[gi] : 0;
        sIdx[tid] = ((unsigned)v < N_NODES) ? v : 0;
    } else if (tid < 2 * TILE_E) {
        int gi = tile0 + tid - TILE_E;
        int v = (gi < N_LABEL) ? eli[N_LABEL + gi] : 0;
        sIdx[tid] = ((unsigned)v < N_NODES) ? v : 0;
    }
    __syncthreads();

    float acc[3][8];
    #pragma unroll
    for (int i = 0; i < 3; i++)
        #pragma unroll
        for (int j = 0; j < 8; j++) acc[i][j] = b1r[j];

    float4* sD4  = (float4*)sm;            // [48] rows, stride 9 f4
    float4* sW14 = (float4*)sm + SD_F4;    // [32] rows, stride 33 f4
    const float4* h4 = (const float4*)g_h;
    const float4* W1g4 = (const float4*)W1;

    for (int k0 = 0; k0 < CH; k0 += 32) {
        #pragma unroll
        for (int it = 0; it < 2; it++) {
            int idx = tid + 256 * it;
            if (idx < TILE_E * 8) {
                int e = idx >> 3, c4 = idx & 7;
                int a = sIdx[e], b = sIdx[TILE_E + e];
                float4 va = h4[(size_t)a * 64 + (k0 >> 2) + c4];
                float4 vb = h4[(size_t)b * 64 + (k0 >> 2) + c4];
                sD4[e * 9 + c4] = make_float4(vb.x - va.x, vb.y - va.y,
                                              vb.z - va.z, vb.w - va.w);
            }
        }
        #pragma unroll
        for (int it = 0; it < 4; it++) {
            int idx = tid + 256 * it;
            int k = idx >> 5, c4 = idx & 31;
            sW14[k * 33 + c4] = W1g4[(size_t)(k0 + k) * 32 + c4];
        }
        __syncthreads();

        #pragma unroll
        for (int k4 = 0; k4 < 8; k4++) {
            float4 a4[3];
            #pragma unroll
            for (int i = 0; i < 3; i++) a4[i] = sD4[(ty * 3 + i) * 9 + k4];
            #pragma unroll
            for (int kk = 0; kk < 4; kk++) {
                int k = k4 * 4 + kk;
                float4 bv0 = sW14[k * 33 + tx * 2];
                float4 bv1 = sW14[k * 33 + tx * 2 + 1];
                #pragma unroll
                for (int i = 0; i < 3; i++) {
                    float av = (kk == 0) ? a4[i].x : (kk == 1) ? a4[i].y
                             : (kk == 2) ? a4[i].z : a4[i].w;
                    acc[i][0] += av * bv0.x; acc[i][1] += av * bv0.y;
                    acc[i][2] += av * bv0.z; acc[i][3] += av * bv0.w;
                    acc[i][4] += av * bv1.x; acc[i][5] += av * bv1.y;
                    acc[i][6] += av * bv1.z; acc[i][7] += av * bv1.w;
                }
            }
        }
        __syncthreads();
    }

    float4* sO4  = (float4*)sm;            // [48] rows, stride 32 f4
    float*  sW2t = sm + SW2T_OFF;          // [32] rows, stride 132 floats
    const float4* sW2t4 = (const float4*)sW2t;

    #pragma unroll
    for (int i = 0; i < 3; i++) {
        int e = ty * 3 + i;
        sO4[e * 32 + tx * 2] = make_float4(fmaxf(acc[i][0], 0.f), fmaxf(acc[i][1], 0.f),
                                           fmaxf(acc[i][2], 0.f), fmaxf(acc[i][3], 0.f));
        sO4[e * 32 + tx * 2 + 1] = make_float4(fmaxf(acc[i][4], 0.f), fmaxf(acc[i][5], 0.f),
                                               fmaxf(acc[i][6], 0.f), fmaxf(acc[i][7], 0.f));
    }
    #pragma unroll
    for (int it = 0; it < 16; it++) {
        int idx = tid + 256 * it;
        int k = idx >> 5, j2 = idx & 31;
        sW2t[j2 * 132 + k] = W2[idx];
    }
    __syncthreads();

    #pragma unroll
    for (int i = 0; i < 6; i++) {
        int e = (tid >> 5) + 8 * i;
        float acc2 = b2r;
        #pragma unroll
        for (int k4 = 0; k4 < 32; k4++) {
            float4 ov = sO4[e * 32 + k4];
            float4 wv = sW2t4[lane * 33 + k4];
            acc2 += ov.x * wv.x + ov.y * wv.y + ov.z * wv.z + ov.w * wv.w;
        }
        float v = fmaxf(acc2, 0.f) * w3r;
        #pragma unroll
        for (int off = 16; off; off >>= 1)
            v += __shfl_xor_sync(0xffffffffu, v, off);
        if (lane == 0 && tile0 + e < N_LABEL) out[tile0 + e] = v + b3r;
    }
}

// ---------------------------------------------------------------------------
// Host: resolve inputs BY ELEMENT COUNT (robust to metadata ordering).
// Launch order puts gemm_xw 6th so ncu -s 5 -c 1 captures a heavy kernel.
// ---------------------------------------------------------------------------
extern "C" void kernel_launch(void* const* d_in, const int* in_sizes, int n_in,
                              void* d_out, int out_size) {
    const float *x = 0, *W_gcn = 0, *b_gcn = 0, *W1 = 0, *b1 = 0, *W2 = 0,
                *b2 = 0, *W3 = 0, *b3 = 0;
    const int *ei = 0, *eli = 0;
    int idx32[2] = {-1, -1};
    int n32 = 0, i128 = -1;

    for (int i = 0; i < n_in; i++) {
        switch (in_sizes[i]) {
            case 25600000: x     = (const float*)d_in[i]; break;
            case 1600000:  ei    = (const int*)d_in[i];   break;
            case 800000:   eli   = (const int*)d_in[i];   break;
            case 65536:    W_gcn = (const float*)d_in[i]; break;
            case 32768:    W1    = (const float*)d_in[i]; break;
            case 4096:     W2    = (const float*)d_in[i]; break;
            case 256:      b_gcn = (const float*)d_in[i]; break;
            case 128:      b1    = (const float*)d_in[i]; i128 = i; break;
            case 32:       if (n32 < 2) idx32[n32] = i; n32++; break;
            case 1:        b3    = (const float*)d_in[i]; break;
            default: break;
        }
    }
    if (n32 >= 2) {
        if (idx32[0] < i128) {
            W3 = (const float*)d_in[idx32[0]];
            b2 = (const float*)d_in[idx32[1]];
        } else {
            b2 = (const float*)d_in[idx32[0]];
            W3 = (const float*)d_in[idx32[1]];
        }
    }
    if (!x)     x     = (const float*)d_in[0];
    if (!ei)    ei    = (const int*)d_in[1];
    if (!eli)   eli   = (const int*)d_in[2];
    if (!W_gcn) W_gcn = (const float*)d_in[3];
    if (!b_gcn) b_gcn = (const float*)d_in[4];
    if (!W1)    W1    = (const float*)d_in[5];
    if (!b1)    b1    = (const float*)d_in[6];
    if (!W2)    W2    = (const float*)d_in[7];
    if (!b2)    b2    = (const float*)d_in[8];
    if (!W3)    W3    = (const float*)d_in[9];
    if (!b3)    b3    = (const float*)d_in[10];
    float* out = (float*)d_out;

    // CSR build (independent of gemm)
    zero_cnt<<<(N_NODES + 255) / 256, 256>>>();
    hist<<<(N_EDGES + 255) / 256, 256>>>(ei);
    scan1<<<NBLK_SCAN, SCAN_CHUNK>>>();
    scan2<<<1, 256>>>();
    scan3<<<NBLK_SCAN, SCAN_CHUNK>>>();

    // 6th launch: the heavy GEMM (for ncu -s 5 -c 1)
    dim3 ggrid(CH / 64, (N_NODES + 63) / 64);
    gemm_xw<<<ggrid, 256>>>(x, W_gcn);

    fill<<<(N_EDGES + 255) / 256, 256>>>(ei);
    gather<<<(N_NODES + 7) / 8, 256>>>(b_gcn);

    mlp_kernel<<<(N_LABEL + TILE_E - 1) / TILE_E, 256>>>(eli, W1, b1, W2, b2,
                                                         W3, b3, out);
}

// round 8
// speedup vs baseline: 2.4829x; 2.0974x over previous
#include <cuda_runtime.h>

#define N_NODES 100000
#define N_EDGES 800000
#define N_LABEL 400000
#define CH      256
#define H1      128
#define H2      32

#define SCAN_CHUNK 512
#define NBLK_SCAN  ((N_NODES + SCAN_CHUNK - 1) / SCAN_CHUNK)   // 196

// Scratch (module-load allocated; allowed per harness rules)
__device__ __align__(16) float g_xw[(size_t)N_NODES * CH];
__device__ __align__(16) float g_h[(size_t)N_NODES * CH];
__device__ float g_dis[N_NODES];
__device__ int   g_cnt[N_NODES];
__device__ int   g_rowptr[N_NODES + 1];
__device__ int   g_cursor[N_NODES];
__device__ int   g_csrc[N_EDGES];
__device__ int   g_partial[NBLK_SCAN];
__device__ int   g_poff[NBLK_SCAN];

// ---------------------------------------------------------------------------
// tf32 mma helpers (m16n8k8, row.col, fp32 accumulate)
// ---------------------------------------------------------------------------
__device__ __forceinline__ unsigned f2tf(float f) {
    unsigned r;
    asm("cvt.rna.tf32.f32 %0, %1;" : "=r"(r) : "f"(f));
    return r;
}

__device__ __forceinline__ void mma_tf32(float* c, const unsigned* a,
                                         unsigned b0, unsigned b1) {
    asm("mma.sync.aligned.m16n8k8.row.col.f32.tf32.tf32.f32 "
        "{%0,%1,%2,%3},{%4,%5,%6,%7},{%8,%9},{%0,%1,%2,%3};"
        : "+f"(c[0]), "+f"(c[1]), "+f"(c[2]), "+f"(c[3])
        : "r"(a[0]), "r"(a[1]), "r"(a[2]), "r"(a[3]), "r"(b0), "r"(b1));
}

// ---------------------------------------------------------------------------
// xw = x @ W_gcn via tf32 mma. Block tile 128M x 64N, 8 warps (4m x 2n),
// warp tile 32x32 (2 m16-tiles x 4 n8-tiles). K-chunks of 32.
// sA stride 36 fl, sB stride 72 fl -> conflict-free fragment loads.
// ---------------------------------------------------------------------------
__global__ void __launch_bounds__(256)
gemm_xw(const float* __restrict__ X, const float* __restrict__ W) {
    __shared__ __align__(16) float sA[128 * 36];
    __shared__ __align__(16) float sB[32 * 72];
    const int tid = threadIdx.x;
    const int lane = tid & 31, warp = tid >> 5;
    const int warp_m = warp >> 1, warp_n = warp & 1;
    const int row0 = blockIdx.y * 128, col0 = blockIdx.x * 64;
    const int lr = lane >> 2, lc = lane & 3;

    float c[2][4][4];
    #pragma unroll
    for (int mt = 0; mt < 2; mt++)
        #pragma unroll
        for (int nt = 0; nt < 4; nt++)
            #pragma unroll
            for (int i = 0; i < 4; i++) c[mt][nt][i] = 0.f;

    float4* sA4 = (float4*)sA;
    float4* sB4 = (float4*)sB;

    for (int k0 = 0; k0 < CH; k0 += 32) {
        #pragma unroll
        for (int it = 0; it < 4; it++) {
            int idx = tid + 256 * it;           // 1024 f4
            int r = idx >> 3, c4 = idx & 7;
            int grow = row0 + r;
            float4 v = make_float4(0.f, 0.f, 0.f, 0.f);
            if (grow < N_NODES)
                v = *(const float4*)&X[(size_t)grow * CH + k0 + c4 * 4];
            sA4[r * 9 + c4] = v;
        }
        #pragma unroll
        for (int it = 0; it < 2; it++) {
            int idx = tid + 256 * it;           // 512 f4
            int k = idx >> 4, c4 = idx & 15;
            sB4[k * 18 + c4] = *(const float4*)&W[(size_t)(k0 + k) * CH + col0 + c4 * 4];
        }
        __syncthreads();

        #pragma unroll
        for (int k8 = 0; k8 < 4; k8++) {
            int kc = k8 * 8 + lc;
            unsigned a[2][4];
            #pragma unroll
            for (int mt = 0; mt < 2; mt++) {
                int r = warp_m * 32 + mt * 16 + lr;
                a[mt][0] = f2tf(sA[r * 36 + kc]);
                a[mt][1] = f2tf(sA[(r + 8) * 36 + kc]);
                a[mt][2] = f2tf(sA[r * 36 + kc + 4]);
                a[mt][3] = f2tf(sA[(r + 8) * 36 + kc + 4]);
            }
            #pragma unroll
            for (int nt = 0; nt < 4; nt++) {
                int cb = warp_n * 32 + nt * 8 + lr;
                unsigned b0 = f2tf(sB[kc * 72 + cb]);
                unsigned b1 = f2tf(sB[(kc + 4) * 72 + cb]);
                mma_tf32(c[0][nt], a[0], b0, b1);
                mma_tf32(c[1][nt], a[1], b0, b1);
            }
        }
        __syncthreads();
    }

    #pragma unroll
    for (int mt = 0; mt < 2; mt++) {
        int r0 = row0 + warp_m * 32 + mt * 16 + lr;
        #pragma unroll
        for (int nt = 0; nt < 4; nt++) {
            int cc = col0 + warp_n * 32 + nt * 8 + 2 * lc;
            if (r0 < N_NODES)
                *(float2*)&g_xw[(size_t)r0 * CH + cc] = make_float2(c[mt][nt][0], c[mt][nt][1]);
            if (r0 + 8 < N_NODES)
                *(float2*)&g_xw[(size_t)(r0 + 8) * CH + cc] = make_float2(c[mt][nt][2], c[mt][nt][3]);
        }
    }
}

// ---------------------------------------------------------------------------
// CSR build: histogram -> 3-pass exclusive scan -> bucket fill
// ---------------------------------------------------------------------------
__global__ void zero_cnt() {
    int i = blockIdx.x * blockDim.x + threadIdx.x;
    if (i < N_NODES) g_cnt[i] = 0;
}

__global__ void hist(const int* __restrict__ ei) {
    int e = blockIdx.x * blockDim.x + threadIdx.x;
    if (e >= N_EDGES) return;
    int d = ei[N_EDGES + e];
    if ((unsigned)d < N_NODES) atomicAdd(&g_cnt[d], 1);
}

__global__ void __launch_bounds__(SCAN_CHUNK) scan1() {
    __shared__ int s[SCAN_CHUNK];
    int tid = threadIdx.x;
    int i = blockIdx.x * SCAN_CHUNK + tid;
    s[tid] = (i < N_NODES) ? g_cnt[i] : 0;
    __syncthreads();
    #pragma unroll
    for (int off = SCAN_CHUNK / 2; off > 0; off >>= 1) {
        if (tid < off) s[tid] += s[tid + off];
        __syncthreads();
    }
    if (tid == 0) g_partial[blockIdx.x] = s[0];
}

__global__ void __launch_bounds__(256) scan2() {
    __shared__ int s[256];
    int tid = threadIdx.x;
    int v = (tid < NBLK_SCAN) ? g_partial[tid] : 0;
    s[tid] = v;
    __syncthreads();
    #pragma unroll
    for (int off = 1; off < 256; off <<= 1) {
        int t = (tid >= off) ? s[tid - off] : 0;
        __syncthreads();
        s[tid] += t;
        __syncthreads();
    }
    if (tid < NBLK_SCAN) g_poff[tid] = s[tid] - v;
    if (tid == NBLK_SCAN - 1) g_rowptr[N_NODES] = s[tid];
}

__global__ void __launch_bounds__(SCAN_CHUNK) scan3() {
    __shared__ int s[SCAN_CHUNK];
    int tid = threadIdx.x;
    int i = blockIdx.x * SCAN_CHUNK + tid;
    int c = (i < N_NODES) ? g_cnt[i] : 0;
    s[tid] = c;
    __syncthreads();
    #pragma unroll
    for (int off = 1; off < SCAN_CHUNK; off <<= 1) {
        int t = (tid >= off) ? s[tid - off] : 0;
        __syncthreads();
        s[tid] += t;
        __syncthreads();
    }
    if (i < N_NODES) {
        int excl = g_poff[blockIdx.x] + s[tid] - c;
        g_rowptr[i] = excl;
        g_cursor[i] = excl;
        g_dis[i] = rsqrtf((float)(c + 1));
    }
}

__global__ void fill(const int* __restrict__ ei) {
    int e = blockIdx.x * blockDim.x + threadIdx.x;
    if (e >= N_EDGES) return;
    int src = ei[e];
    int dst = ei[N_EDGES + e];
    if ((unsigned)src >= N_NODES || (unsigned)dst >= N_NODES) return;
    int p = atomicAdd(&g_cursor[dst], 1);
    g_csrc[p] = src;
}

// ---------------------------------------------------------------------------
// Gather: warp per node. h[i] = b + dis[i]*(dis[i]*xw[i] + sum dis[s]*xw[s])
// ---------------------------------------------------------------------------
__global__ void __launch_bounds__(256) gather(const float* __restrict__ b_gcn) {
    int node = blockIdx.x * 8 + (threadIdx.x >> 5);
    if (node >= N_NODES) return;
    int lane = threadIdx.x & 31;
    const float4* xw4 = (const float4*)g_xw;
    const float4* b4  = (const float4*)b_gcn;

    float di = g_dis[node];
    float4 v0 = xw4[(size_t)node * 64 + lane];
    float4 v1 = xw4[(size_t)node * 64 + 32 + lane];
    float4 acc0 = make_float4(di * v0.x, di * v0.y, di * v0.z, di * v0.w);
    float4 acc1 = make_float4(di * v1.x, di * v1.y, di * v1.z, di * v1.w);

    int beg = g_rowptr[node], end = g_rowptr[node + 1];
    for (int j = beg; j < end; j++) {
        int s = g_csrc[j];
        float cc = g_dis[s];
        float4 w0 = xw4[(size_t)s * 64 + lane];
        float4 w1 = xw4[(size_t)s * 64 + 32 + lane];
        acc0.x += cc * w0.x; acc0.y += cc * w0.y;
        acc0.z += cc * w0.z; acc0.w += cc * w0.w;
        acc1.x += cc * w1.x; acc1.y += cc * w1.y;
        acc1.z += cc * w1.z; acc1.w += cc * w1.w;
    }

    float4 bv0 = b4[lane], bv1 = b4[lane + 32];
    float4* h4 = (float4*)g_h;
    h4[(size_t)node * 64 + lane] =
        make_float4(bv0.x + di * acc0.x, bv0.y + di * acc0.y,
                    bv0.z + di * acc0.z, bv0.w + di * acc0.w);
    h4[(size_t)node * 64 + 32 + lane] =
        make_float4(bv1.x + di * acc1.x, bv1.y + di * acc1.y,
                    bv1.z + di * acc1.z, bv1.w + di * acc1.w);
}

// ---------------------------------------------------------------------------
// Fused MLP, layer-1 on tensor cores (tf32 mma). TILE_E=64 edges/block,
// 8 warps (2m x 4n), warp tile 32x32. Dynamic smem (union):
//   Phase A: sD[64] stride 36 fl + sW1[32] stride 136 fl  (6656 fl)
//   Phase B: sO[64] stride 132 fl + sW2t[32] stride 132 fl (12672 fl = 50.7KB)
// ---------------------------------------------------------------------------
#define TILE_E    64
#define SD_STRF   36
#define SW1_STRF  136
#define SO_STRF   132
#define SO_FL     (TILE_E * SO_STRF)             // 8448
#define MLP_SMEM_F (SO_FL + 32 * 132)            // 12672 floats
#define MLP_SMEM_B (MLP_SMEM_F * 4)              // 50688 bytes

__global__ void __launch_bounds__(256)
mlp_kernel(const int* __restrict__ eli,
           const float* __restrict__ W1, const float* __restrict__ b1,
           const float* __restrict__ W2, const float* __restrict__ b2,
           const float* __restrict__ W3, const float* __restrict__ b3,
           float* __restrict__ out) {
    extern __shared__ __align__(16) float sm[];
    __shared__ int sIdx[2 * TILE_E];

    const int tid  = threadIdx.x;
    const int lane = tid & 31, warp = tid >> 5;
    const int warp_m = warp >> 2, warp_n = warp & 3;   // 2 x 4
    const int lr = lane >> 2, lc = lane & 3;
    const int tile0 = blockIdx.x * TILE_E;

    const float b2r = b2[lane];
    const float w3r = W3[lane];
    const float b3r = b3[0];

    if (tid < TILE_E) {
        int v = eli[tile0 + tid];
        sIdx[tid] = ((unsigned)v < N_NODES) ? v : 0;
    } else if (tid < 2 * TILE_E) {
        int v = eli[N_LABEL + tile0 + tid - TILE_E];
        sIdx[tid] = ((unsigned)v < N_NODES) ? v : 0;
    }
    __syncthreads();

    float c[2][4][4];
    #pragma unroll
    for (int mt = 0; mt < 2; mt++)
        #pragma unroll
        for (int nt = 0; nt < 4; nt++)
            #pragma unroll
            for (int i = 0; i < 4; i++) c[mt][nt][i] = 0.f;

    float* sD  = sm;                       // [64][36]
    float* sW1 = sm + TILE_E * SD_STRF;    // [32][136]
    float4* sD4  = (float4*)sD;            // stride 9 f4
    float4* sW14 = (float4*)sW1;           // stride 34 f4
    const float4* h4 = (const float4*)g_h;
    const float4* W1g4 = (const float4*)W1;

    for (int k0 = 0; k0 < CH; k0 += 32) {
        // stage D chunk: 64 edges x 8 f4 = 512 f4
        #pragma unroll
        for (int it = 0; it < 2; it++) {
            int idx = tid + 256 * it;
            int e = idx >> 3, c4 = idx & 7;
            int a = sIdx[e], b = sIdx[TILE_E + e];
            float4 va = h4[(size_t)a * 64 + (k0 >> 2) + c4];
            float4 vb = h4[(size_t)b * 64 + (k0 >> 2) + c4];
            sD4[e * 9 + c4] = make_float4(vb.x - va.x, vb.y - va.y,
                                          vb.z - va.z, vb.w - va.w);
        }
        // stage W1 chunk: 32 rows x 32 f4 = 1024 f4
        #pragma unroll
        for (int it = 0; it < 4; it++) {
            int idx = tid + 256 * it;
            int k = idx >> 5, c4 = idx & 31;
            sW14[k * 34 + c4] = W1g4[(size_t)(k0 + k) * 32 + c4];
        }
        __syncthreads();

        #pragma unroll
        for (int k8 = 0; k8 < 4; k8++) {
            int kc = k8 * 8 + lc;
            unsigned a[2][4];
            #pragma unroll
            for (int mt = 0; mt < 2; mt++) {
                int r = warp_m * 32 + mt * 16 + lr;
                a[mt][0] = f2tf(sD[r * SD_STRF + kc]);
                a[mt][1] = f2tf(sD[(r + 8) * SD_STRF + kc]);
                a[mt][2] = f2tf(sD[r * SD_STRF + kc + 4]);
                a[mt][3] = f2tf(sD[(r + 8) * SD_STRF + kc + 4]);
            }
            #pragma unroll
            for (int nt = 0; nt < 4; nt++) {
                int cb = warp_n * 32 + nt * 8 + lr;
                unsigned b0 = f2tf(sW1[kc * SW1_STRF + cb]);
                unsigned b1 = f2tf(sW1[(kc + 4) * SW1_STRF + cb]);
                mma_tf32(c[0][nt], a[0], b0, b1);
                mma_tf32(c[1][nt], a[1], b0, b1);
            }
        }
        __syncthreads();
    }

    // Phase B: bias+relu -> sO, stage W2^T, SIMT layers 2+3
    float* sO   = sm;                  // [64][132]
    float* sW2t = sm + SO_FL;          // [32][132]
    const float4* sO4   = (const float4*)sO;    // stride 33 f4
    const float4* sW2t4 = (const float4*)sW2t;  // stride 33 f4

    #pragma unroll
    for (int mt = 0; mt < 2; mt++) {
        int r0 = warp_m * 32 + mt * 16 + lr;
        #pragma unroll
        for (int nt = 0; nt < 4; nt++) {
            int c0 = warp_n * 32 + nt * 8 + 2 * lc;
            float bi0 = b1[c0], bi1 = b1[c0 + 1];
            sO[r0 * SO_STRF + c0]       = fmaxf(c[mt][nt][0] + bi0, 0.f);
            sO[r0 * SO_STRF + c0 + 1]   = fmaxf(c[mt][nt][1] + bi1, 0.f);
            sO[(r0 + 8) * SO_STRF + c0]     = fmaxf(c[mt][nt][2] + bi0, 0.f);
            sO[(r0 + 8) * SO_STRF + c0 + 1] = fmaxf(c[mt][nt][3] + bi1, 0.f);
        }
    }
    #pragma unroll
    for (int it = 0; it < 16; it++) {
        int idx = tid + 256 * it;          // 4096 elems of W2 [128][32]
        int k = idx >> 5, j2 = idx & 31;
        sW2t[j2 * 132 + k] = W2[idx];
    }
    __syncthreads();

    #pragma unroll
    for (int i = 0; i < 8; i++) {
        int e = warp + 8 * i;              // warp-uniform edge, lane = j2
        float acc2 = b2r;
        #pragma unroll
        for (int k4 = 0; k4 < 32; k4++) {
            float4 ov = sO4[e * 33 + k4];
            float4 wv = sW2t4[lane * 33 + k4];
            acc2 += ov.x * wv.x + ov.y * wv.y + ov.z * wv.z + ov.w * wv.w;
        }
        float v = fmaxf(acc2, 0.f) * w3r;
        #pragma unroll
        for (int off = 16; off; off >>= 1)
            v += __shfl_xor_sync(0xffffffffu, v, off);
        if (lane == 0) out[tile0 + e] = v + b3r;
    }
}

// ---------------------------------------------------------------------------
// Host: resolve inputs BY ELEMENT COUNT; gemm_xw is launch #4 (ncu window).
// ---------------------------------------------------------------------------
extern "C" void kernel_launch(void* const* d_in, const int* in_sizes, int n_in,
                              void* d_out, int out_size) {
    const float *x = 0, *W_gcn = 0, *b_gcn = 0, *W1 = 0, *b1 = 0, *W2 = 0,
                *b2 = 0, *W3 = 0, *b3 = 0;
    const int *ei = 0, *eli = 0;
    int idx32[2] = {-1, -1};
    int n32 = 0, i128 = -1;

    for (int i = 0; i < n_in; i++) {
        switch (in_sizes[i]) {
            case 25600000: x     = (const float*)d_in[i]; break;
            case 1600000:  ei    = (const int*)d_in[i];   break;
            case 800000:   eli   = (const int*)d_in[i];   break;
            case 65536:    W_gcn = (const float*)d_in[i]; break;
            case 32768:    W1    = (const float*)d_in[i]; break;
            case 4096:     W2    = (const float*)d_in[i]; break;
            case 256:      b_gcn = (const float*)d_in[i]; break;
            case 128:      b1    = (const float*)d_in[i]; i128 = i; break;
            case 32:       if (n32 < 2) idx32[n32] = i; n32++; break;
            case 1:        b3    = (const float*)d_in[i]; break;
            default: break;
        }
    }
    if (n32 >= 2) {
        if (idx32[0] < i128) {
            W3 = (const float*)d_in[idx32[0]];
            b2 = (const float*)d_in[idx32[1]];
        } else {
            b2 = (const float*)d_in[idx32[0]];
            W3 = (const float*)d_in[idx32[1]];
        }
    }
    if (!x)     x     = (const float*)d_in[0];
    if (!ei)    ei    = (const int*)d_in[1];
    if (!eli)   eli   = (const int*)d_in[2];
    if (!W_gcn) W_gcn = (const float*)d_in[3];
    if (!b_gcn) b_gcn = (const float*)d_in[4];
    if (!W1)    W1    = (const float*)d_in[5];
    if (!b1)    b1    = (const float*)d_in[6];
    if (!W2)    W2    = (const float*)d_in[7];
    if (!b2)    b2    = (const float*)d_in[8];
    if (!W3)    W3    = (const float*)d_in[9];
    if (!b3)    b3    = (const float*)d_in[10];
    float* out = (float*)d_out;

    cudaFuncSetAttribute(mlp_kernel, cudaFuncAttributeMaxDynamicSharedMemorySize,
                         MLP_SMEM_B);

    zero_cnt<<<(N_NODES + 255) / 256, 256>>>();
    hist<<<(N_EDGES + 255) / 256, 256>>>(ei);
    scan1<<<NBLK_SCAN, SCAN_CHUNK>>>();

    // launch #4: heavy GEMM (ncu window lands here)
    dim3 ggrid(CH / 64, (N_NODES + 127) / 128);
    gemm_xw<<<ggrid, 256>>>(x, W_gcn);

    scan2<<<1, 256>>>();
    scan3<<<NBLK_SCAN, SCAN_CHUNK>>>();
    fill<<<(N_EDGES + 255) / 256, 256>>>(ei);
    gather<<<(N_NODES + 7) / 8, 256>>>(b_gcn);

    mlp_kernel<<<N_LABEL / TILE_E, 256, MLP_SMEM_B>>>(eli, W1, b1, W2, b2,
                                                      W3, b3, out);
}

// round 9
// speedup vs baseline: 5.6396x; 2.2714x over previous
#include <cuda_runtime.h>

#define N_NODES 100000
#define N_EDGES 800000
#define N_LABEL 400000
#define CH      256
#define H1      128
#define H2      32

#define SCAN_CHUNK 512
#define NBLK_SCAN  ((N_NODES + SCAN_CHUNK - 1) / SCAN_CHUNK)   // 196

// Scratch (module-load allocated; allowed per harness rules)
__device__ __align__(16) float g_xw[(size_t)N_NODES * CH];
__device__ __align__(16) float g_h[(size_t)N_NODES * CH];
__device__ __align__(16) float g_z[(size_t)N_NODES * H1];
__device__ float g_dis[N_NODES];
__device__ int   g_cnt[N_NODES];
__device__ int   g_rowptr[N_NODES + 1];
__device__ int   g_cursor[N_NODES];
__device__ int   g_csrc[N_EDGES];
__device__ int   g_partial[NBLK_SCAN];
__device__ int   g_poff[NBLK_SCAN];

// ---------------------------------------------------------------------------
// tf32 mma helpers (m16n8k8, row.col, fp32 accumulate)
// ---------------------------------------------------------------------------
__device__ __forceinline__ unsigned f2tf(float f) {
    unsigned r;
    asm("cvt.rna.tf32.f32 %0, %1;" : "=r"(r) : "f"(f));
    return r;
}

__device__ __forceinline__ void mma_tf32(float* c, const unsigned* a,
                                         unsigned b0, unsigned b1) {
    asm("mma.sync.aligned.m16n8k8.row.col.f32.tf32.tf32.f32 "
        "{%0,%1,%2,%3},{%4,%5,%6,%7},{%8,%9},{%0,%1,%2,%3};"
        : "+f"(c[0]), "+f"(c[1]), "+f"(c[2]), "+f"(c[3])
        : "r"(a[0]), "r"(a[1]), "r"(a[2]), "r"(a[3]), "r"(b0), "r"(b1));
}

// ---------------------------------------------------------------------------
// Generic tf32 GEMM: OUT[r, col0:col0+64] = X[100000x256] @ W[256 x wstride].
// Block tile 128M x 64N, 8 warps (4m x 2n), warp tile 32x32. K-chunks of 32.
// smem holds PRE-CONVERTED tf32 bits (cvt once at staging, not per fragment).
// ---------------------------------------------------------------------------
__global__ void __launch_bounds__(256)
gemm_tf32(const float* __restrict__ X, const float* __restrict__ W,
          float* __restrict__ OUT, int wstride) {
    __shared__ __align__(16) unsigned sA[128 * 36];
    __shared__ __align__(16) unsigned sB[32 * 72];
    const int tid = threadIdx.x;
    const int lane = tid & 31, warp = tid >> 5;
    const int warp_m = warp >> 1, warp_n = warp & 1;
    const int row0 = blockIdx.y * 128, col0 = blockIdx.x * 64;
    const int lr = lane >> 2, lc = lane & 3;

    float c[2][4][4];
    #pragma unroll
    for (int mt = 0; mt < 2; mt++)
        #pragma unroll
        for (int nt = 0; nt < 4; nt++)
            #pragma unroll
            for (int i = 0; i < 4; i++) c[mt][nt][i] = 0.f;

    uint4* sA4 = (uint4*)sA;
    uint4* sB4 = (uint4*)sB;

    for (int k0 = 0; k0 < CH; k0 += 32) {
        #pragma unroll
        for (int it = 0; it < 4; it++) {
            int idx = tid + 256 * it;           // 1024 f4
            int r = idx >> 3, c4 = idx & 7;
            int grow = row0 + r;
            float4 v = make_float4(0.f, 0.f, 0.f, 0.f);
            if (grow < N_NODES)
                v = *(const float4*)&X[(size_t)grow * CH + k0 + c4 * 4];
            sA4[r * 9 + c4] = make_uint4(f2tf(v.x), f2tf(v.y), f2tf(v.z), f2tf(v.w));
        }
        #pragma unroll
        for (int it = 0; it < 2; it++) {
            int idx = tid + 256 * it;           // 512 f4
            int k = idx >> 4, c4 = idx & 15;
            float4 v = *(const float4*)&W[(size_t)(k0 + k) * wstride + col0 + c4 * 4];
            sB4[k * 18 + c4] = make_uint4(f2tf(v.x), f2tf(v.y), f2tf(v.z), f2tf(v.w));
        }
        __syncthreads();

        #pragma unroll
        for (int k8 = 0; k8 < 4; k8++) {
            int kc = k8 * 8 + lc;
            unsigned a[2][4];
            #pragma unroll
            for (int mt = 0; mt < 2; mt++) {
                int r = warp_m * 32 + mt * 16 + lr;
                a[mt][0] = sA[r * 36 + kc];
                a[mt][1] = sA[(r + 8) * 36 + kc];
                a[mt][2] = sA[r * 36 + kc + 4];
                a[mt][3] = sA[(r + 8) * 36 + kc + 4];
            }
            #pragma unroll
            for (int nt = 0; nt < 4; nt++) {
                int cb = warp_n * 32 + nt * 8 + lr;
                unsigned b0 = sB[kc * 72 + cb];
                unsigned b1 = sB[(kc + 4) * 72 + cb];
                mma_tf32(c[0][nt], a[0], b0, b1);
                mma_tf32(c[1][nt], a[1], b0, b1);
            }
        }
        __syncthreads();
    }

    #pragma unroll
    for (int mt = 0; mt < 2; mt++) {
        int r0 = row0 + warp_m * 32 + mt * 16 + lr;
        #pragma unroll
        for (int nt = 0; nt < 4; nt++) {
            int cc = col0 + warp_n * 32 + nt * 8 + 2 * lc;
            if (r0 < N_NODES)
                *(float2*)&OUT[(size_t)r0 * wstride + cc] = make_float2(c[mt][nt][0], c[mt][nt][1]);
            if (r0 + 8 < N_NODES)
                *(float2*)&OUT[(size_t)(r0 + 8) * wstride + cc] = make_float2(c[mt][nt][2], c[mt][nt][3]);
        }
    }
}

// ---------------------------------------------------------------------------
// CSR build: histogram -> 3-pass exclusive scan -> bucket fill
// ---------------------------------------------------------------------------
__global__ void zero_cnt() {
    int i = blockIdx.x * blockDim.x + threadIdx.x;
    if (i < N_NODES) g_cnt[i] = 0;
}

__global__ void hist(const int* __restrict__ ei) {
    int e = blockIdx.x * blockDim.x + threadIdx.x;
    if (e >= N_EDGES) return;
    int d = ei[N_EDGES + e];
    if ((unsigned)d < N_NODES) atomicAdd(&g_cnt[d], 1);
}

__global__ void __launch_bounds__(SCAN_CHUNK) scan1() {
    __shared__ int s[SCAN_CHUNK];
    int tid = threadIdx.x;
    int i = blockIdx.x * SCAN_CHUNK + tid;
    s[tid] = (i < N_NODES) ? g_cnt[i] : 0;
    __syncthreads();
    #pragma unroll
    for (int off = SCAN_CHUNK / 2; off > 0; off >>= 1) {
        if (tid < off) s[tid] += s[tid + off];
        __syncthreads();
    }
    if (tid == 0) g_partial[blockIdx.x] = s[0];
}

__global__ void __launch_bounds__(256) scan2() {
    __shared__ int s[256];
    int tid = threadIdx.x;
    int v = (tid < NBLK_SCAN) ? g_partial[tid] : 0;
    s[tid] = v;
    __syncthreads();
    #pragma unroll
    for (int off = 1; off < 256; off <<= 1) {
        int t = (tid >= off) ? s[tid - off] : 0;
        __syncthreads();
        s[tid] += t;
        __syncthreads();
    }
    if (tid < NBLK_SCAN) g_poff[tid] = s[tid] - v;
    if (tid == NBLK_SCAN - 1) g_rowptr[N_NODES] = s[tid];
}

__global__ void __launch_bounds__(SCAN_CHUNK) scan3() {
    __shared__ int s[SCAN_CHUNK];
    int tid = threadIdx.x;
    int i = blockIdx.x * SCAN_CHUNK + tid;
    int c = (i < N_NODES) ? g_cnt[i] : 0;
    s[tid] = c;
    __syncthreads();
    #pragma unroll
    for (int off = 1; off < SCAN_CHUNK; off <<= 1) {
        int t = (tid >= off) ? s[tid - off] : 0;
        __syncthreads();
        s[tid] += t;
        __syncthreads();
    }
    if (i < N_NODES) {
        int excl = g_poff[blockIdx.x] + s[tid] - c;
        g_rowptr[i] = excl;
        g_cursor[i] = excl;
        g_dis[i] = rsqrtf((float)(c + 1));
    }
}

__global__ void fill(const int* __restrict__ ei) {
    int e = blockIdx.x * blockDim.x + threadIdx.x;
    if (e >= N_EDGES) return;
    int src = ei[e];
    int dst = ei[N_EDGES + e];
    if ((unsigned)src >= N_NODES || (unsigned)dst >= N_NODES) return;
    int p = atomicAdd(&g_cursor[dst], 1);
    g_csrc[p] = src;
}

// ---------------------------------------------------------------------------
// Gather: warp per node. h[i] = b + dis[i]*(dis[i]*xw[i] + sum dis[s]*xw[s])
// ---------------------------------------------------------------------------
__global__ void __launch_bounds__(256) gather(const float* __restrict__ b_gcn) {
    int node = blockIdx.x * 8 + (threadIdx.x >> 5);
    if (node >= N_NODES) return;
    int lane = threadIdx.x & 31;
    const float4* xw4 = (const float4*)g_xw;
    const float4* b4  = (const float4*)b_gcn;

    float di = g_dis[node];
    float4 v0 = xw4[(size_t)node * 64 + lane];
    float4 v1 = xw4[(size_t)node * 64 + 32 + lane];
    float4 acc0 = make_float4(di * v0.x, di * v0.y, di * v0.z, di * v0.w);
    float4 acc1 = make_float4(di * v1.x, di * v1.y, di * v1.z, di * v1.w);

    int beg = g_rowptr[node], end = g_rowptr[node + 1];
    for (int j = beg; j < end; j++) {
        int s = g_csrc[j];
        float cc = g_dis[s];
        float4 w0 = xw4[(size_t)s * 64 + lane];
        float4 w1 = xw4[(size_t)s * 64 + 32 + lane];
        acc0.x += cc * w0.x; acc0.y += cc * w0.y;
        acc0.z += cc * w0.z; acc0.w += cc * w0.w;
        acc1.x += cc * w1.x; acc1.y += cc * w1.y;
        acc1.z += cc * w1.z; acc1.w += cc * w1.w;
    }

    float4 bv0 = b4[lane], bv1 = b4[lane + 32];
    float4* h4 = (float4*)g_h;
    h4[(size_t)node * 64 + lane] =
        make_float4(bv0.x + di * acc0.x, bv0.y + di * acc0.y,
                    bv0.z + di * acc0.z, bv0.w + di * acc0.w);
    h4[(size_t)node * 64 + 32 + lane] =
        make_float4(bv1.x + di * acc1.x, bv1.y + di * acc1.y,
                    bv1.z + di * acc1.z, bv1.w + di * acc1.w);
}

// ---------------------------------------------------------------------------
// Edge MLP: 128 edges/block, 8 warps. o = relu(Z[b]-Z[a]+b1) staged as tf32;
// layer-2 (128->32) on tensor cores (warp = m16, all 32 N-cols, K=128);
// layer-3 + bias folded into the epilogue (intra-warp quad shfl reduce).
//   sO [128][132] tf32 bits (stride 132 == 4 mod 32: conflict-free A frags)
//   sW2[128][40]  tf32 bits (stride 40  == 8 mod 32: conflict-free B frags)
// ---------------------------------------------------------------------------
#define TE2       128
#define SO2_STR   132
#define SW2_STR   40
#define MLP2_SMEM_W (TE2 * SO2_STR + H1 * SW2_STR)    // 22016 words
#define MLP2_SMEM_B (MLP2_SMEM_W * 4)                 // 88064 bytes

__global__ void __launch_bounds__(256)
mlp2_kernel(const int* __restrict__ eli,
            const float* __restrict__ b1, const float* __restrict__ W2,
            const float* __restrict__ b2, const float* __restrict__ W3,
            const float* __restrict__ b3, float* __restrict__ out) {
    extern __shared__ __align__(16) unsigned smu[];
    __shared__ int sIdx[2 * TE2];

    unsigned* sO  = smu;                    // [128][132]
    unsigned* sW2 = smu + TE2 * SO2_STR;    // [128][40]

    const int tid  = threadIdx.x;
    const int lane = tid & 31, warp = tid >> 5;
    const int lr = lane >> 2, lc = lane & 3;
    const int tile0 = blockIdx.x * TE2;

    if (tid < TE2) {
        int v = eli[tile0 + tid];
        sIdx[tid] = ((unsigned)v < N_NODES) ? v : 0;
    } else {
        int v = eli[N_LABEL + tile0 + tid - TE2];
        sIdx[tid] = ((unsigned)v < N_NODES) ? v : 0;
    }
    __syncthreads();

    // stage o = relu(Z[b]-Z[a]+b1) as tf32 bits: 128 edges x 32 f4
    const float4* z4  = (const float4*)g_z;
    const float4* b14 = (const float4*)b1;
    #pragma unroll
    for (int it = 0; it < 16; it++) {
        int idx = tid + 256 * it;
        int e = idx >> 5, c4 = idx & 31;
        int a = sIdx[e], b = sIdx[TE2 + e];
        float4 va = z4[(size_t)a * 32 + c4];
        float4 vb = z4[(size_t)b * 32 + c4];
        float4 bi = b14[c4];
        ((uint4*)sO)[e * 33 + c4] = make_uint4(
            f2tf(fmaxf(vb.x - va.x + bi.x, 0.f)),
            f2tf(fmaxf(vb.y - va.y + bi.y, 0.f)),
            f2tf(fmaxf(vb.z - va.z + bi.z, 0.f)),
            f2tf(fmaxf(vb.w - va.w + bi.w, 0.f)));
    }
    // stage W2 [128][32] -> sW2 stride 40
    #pragma unroll
    for (int it = 0; it < 16; it++) {
        int idx = tid + 256 * it;
        int k = idx >> 5, n = idx & 31;
        sW2[k * SW2_STR + n] = f2tf(W2[idx]);
    }
    __syncthreads();

    // mma: warp handles rows warp*16..+15, all 32 cols (4 n8 tiles), K=128
    float c[4][4];
    #pragma unroll
    for (int nt = 0; nt < 4; nt++)
        #pragma unroll
        for (int i = 0; i < 4; i++) c[nt][i] = 0.f;

    #pragma unroll
    for (int k8 = 0; k8 < 16; k8++) {
        int kc = k8 * 8 + lc;
        int r = warp * 16 + lr;
        unsigned a[4];
        a[0] = sO[r * SO2_STR + kc];
        a[1] = sO[(r + 8) * SO2_STR + kc];
        a[2] = sO[r * SO2_STR + kc + 4];
        a[3] = sO[(r + 8) * SO2_STR + kc + 4];
        #pragma unroll
        for (int nt = 0; nt < 4; nt++) {
            int cb = nt * 8 + lr;
            unsigned b0 = sW2[kc * SW2_STR + cb];
            unsigned b1v = sW2[(kc + 4) * SW2_STR + cb];
            mma_tf32(c[nt], a, b0, b1v);
        }
    }

    // epilogue: +b2, relu, dot W3, quad-shfl reduce, +b3
    const float b3r = b3[0];
    float p0 = 0.f, p1 = 0.f;
    #pragma unroll
    for (int nt = 0; nt < 4; nt++) {
        int n0 = nt * 8 + 2 * lc;
        float b20 = b2[n0], b21 = b2[n0 + 1];
        float w30 = W3[n0], w31 = W3[n0 + 1];
        p0 += fmaxf(c[nt][0] + b20, 0.f) * w30 + fmaxf(c[nt][1] + b21, 0.f) * w31;
        p1 += fmaxf(c[nt][2] + b20, 0.f) * w30 + fmaxf(c[nt][3] + b21, 0.f) * w31;
    }
    p0 += __shfl_xor_sync(0xffffffffu, p0, 1);
    p0 += __shfl_xor_sync(0xffffffffu, p0, 2);
    p1 += __shfl_xor_sync(0xffffffffu, p1, 1);
    p1 += __shfl_xor_sync(0xffffffffu, p1, 2);
    if (lc == 0) {
        int r = tile0 + warp * 16 + lr;
        out[r] = p0 + b3r;
        out[r + 8] = p1 + b3r;
    }
}

// ---------------------------------------------------------------------------
// Host: resolve inputs BY ELEMENT COUNT; gemm_tf32(xw) is launch #4.
// ---------------------------------------------------------------------------
extern "C" void kernel_launch(void* const* d_in, const int* in_sizes, int n_in,
                              void* d_out, int out_size) {
    const float *x = 0, *W_gcn = 0, *b_gcn = 0, *W1 = 0, *b1 = 0, *W2 = 0,
                *b2 = 0, *W3 = 0, *b3 = 0;
    const int *ei = 0, *eli = 0;
    int idx32[2] = {-1, -1};
    int n32 = 0, i128 = -1;

    for (int i = 0; i < n_in; i++) {
        switch (in_sizes[i]) {
            case 25600000: x     = (const float*)d_in[i]; break;
            case 1600000:  ei    = (const int*)d_in[i];   break;
            case 800000:   eli   = (const int*)d_in[i];   break;
            case 65536:    W_gcn = (const float*)d_in[i]; break;
            case 32768:    W1    = (const float*)d_in[i]; break;
            case 4096:     W2    = (const float*)d_in[i]; break;
            case 256:      b_gcn = (const float*)d_in[i]; break;
            case 128:      b1    = (const float*)d_in[i]; i128 = i; break;
            case 32:       if (n32 < 2) idx32[n32] = i; n32++; break;
            case 1:        b3    = (const float*)d_in[i]; break;
            default: break;
        }
    }
    if (n32 >= 2) {
        if (idx32[0] < i128) {
            W3 = (const float*)d_in[idx32[0]];
            b2 = (const float*)d_in[idx32[1]];
        } else {
            b2 = (const float*)d_in[idx32[0]];
            W3 = (const float*)d_in[idx32[1]];
        }
    }
    if (!x)     x     = (const float*)d_in[0];
    if (!ei)    ei    = (const int*)d_in[1];
    if (!eli)   eli   = (const int*)d_in[2];
    if (!W_gcn) W_gcn = (const float*)d_in[3];
    if (!b_gcn) b_gcn = (const float*)d_in[4];
    if (!W1)    W1    = (const float*)d_in[5];
    if (!b1)    b1    = (const float*)d_in[6];
    if (!W2)    W2    = (const float*)d_in[7];
    if (!b2)    b2    = (const float*)d_in[8];
    if (!W3)    W3    = (const float*)d_in[9];
    if (!b3)    b3    = (const float*)d_in[10];
    float* out = (float*)d_out;

    cudaFuncSetAttribute(mlp2_kernel, cudaFuncAttributeMaxDynamicSharedMemorySize,
                         MLP2_SMEM_B);

    float* xw = 0;
    cudaGetSymbolAddress((void**)&xw, g_xw);
    float* h = 0;
    cudaGetSymbolAddress((void**)&h, g_h);
    float* z = 0;
    cudaGetSymbolAddress((void**)&z, g_z);

    zero_cnt<<<(N_NODES + 255) / 256, 256>>>();
    hist<<<(N_EDGES + 255) / 256, 256>>>(ei);
    scan1<<<NBLK_SCAN, SCAN_CHUNK>>>();

    // launch #4 (ncu window): xw = x @ W_gcn
    dim3 g1(CH / 64, (N_NODES + 127) / 128);
    gemm_tf32<<<g1, 256>>>(x, W_gcn, xw, CH);

    scan2<<<1, 256>>>();
    scan3<<<NBLK_SCAN, SCAN_CHUNK>>>();
    fill<<<(N_EDGES + 255) / 256, 256>>>(ei);
    gather<<<(N_NODES + 7) / 8, 256>>>(b_gcn);

    // Z = h @ W1
    dim3 g2(H1 / 64, (N_NODES + 127) / 128);
    gemm_tf32<<<g2, 256>>>(h, W1, z, H1);

    mlp2_kernel<<<N_LABEL / TE2, 256, MLP2_SMEM_B>>>(eli, b1, W2, b2, W3, b3, out);
}

// round 10
// speedup vs baseline: 6.7847x; 1.2030x over previous
#include <cuda_runtime.h>

#define N_NODES 100000
#define N_EDGES 800000
#define N_LABEL 400000
#define CH      256
#define H1      128
#define H2      32

#define SCAN_CHUNK 512
#define NBLK_SCAN  ((N_NODES + SCAN_CHUNK - 1) / SCAN_CHUNK)   // 196

// Scratch (module-load allocated; allowed per harness rules)
__device__ __align__(16) float g_xw[(size_t)N_NODES * CH];
__device__ __align__(16) float g_h[(size_t)N_NODES * CH];
__device__ __align__(16) float g_z[(size_t)N_NODES * H1];
__device__ float g_dis[N_NODES];
__device__ int   g_cnt[N_NODES];
__device__ int   g_rowptr[N_NODES + 1];
__device__ int   g_cursor[N_NODES];
__device__ int   g_csrc[N_EDGES];
__device__ int   g_partial[NBLK_SCAN];
__device__ int   g_poff[NBLK_SCAN];

// ---------------------------------------------------------------------------
// tf32 mma helpers (m16n8k8, row.col, fp32 accumulate)
// ---------------------------------------------------------------------------
__device__ __forceinline__ unsigned f2tf(float f) {
    unsigned r;
    asm("cvt.rna.tf32.f32 %0, %1;" : "=r"(r) : "f"(f));
    return r;
}

__device__ __forceinline__ uint4 f2tf4(float4 v) {
    return make_uint4(f2tf(v.x), f2tf(v.y), f2tf(v.z), f2tf(v.w));
}

__device__ __forceinline__ void mma_tf32(float* c, const unsigned* a,
                                         unsigned b0, unsigned b1) {
    asm("mma.sync.aligned.m16n8k8.row.col.f32.tf32.tf32.f32 "
        "{%0,%1,%2,%3},{%4,%5,%6,%7},{%8,%9},{%0,%1,%2,%3};"
        : "+f"(c[0]), "+f"(c[1]), "+f"(c[2]), "+f"(c[3])
        : "r"(a[0]), "r"(a[1]), "r"(a[2]), "r"(a[3]), "r"(b0), "r"(b1));
}

// ---------------------------------------------------------------------------
// Pipelined tf32 GEMM: OUT[.., col0:col0+64] = X[Nx256] @ W[256 x WS].
// Block tile 128M x 64N, 8 warps (4m x 2n), warp tile 32x32, k-chunks of 32.
// Register-prefetch + double-buffered smem (tf32 bits, cvt at staging),
// ONE __syncthreads per chunk. Strides: sA 36 (banks 4*lr+lc), sB 72
// (banks 8*lc+lr) -> conflict-free fragment loads.
// ---------------------------------------------------------------------------
#define GBUF_F   (128 * 36 + 32 * 72)          // 6912 words per buffer
#define GSMEM_B  (2 * GBUF_F * 4)              // 55296 bytes

template<int WS>
__global__ void __launch_bounds__(256)
gemm_tf32(const float* __restrict__ X, const float* __restrict__ W,
          float* __restrict__ OUT) {
    extern __shared__ __align__(16) unsigned smu[];
    const int tid = threadIdx.x;
    const int lane = tid & 31, warp = tid >> 5;
    const int warp_m = warp >> 1, warp_n = warp & 1;
    const int row0 = blockIdx.y * 128, col0 = blockIdx.x * 64;
    const int lr = lane >> 2, lc = lane & 3;

    // per-thread staging coordinates
    const int ar = tid >> 3, ac4 = tid & 7;          // A: rows ar+32*it, col ac4*4
    const int bk = tid >> 4, bc4 = tid & 15;         // B: rows bk+16*it, col bc4*4

    float c[2][4][4];
    #pragma unroll
    for (int mt = 0; mt < 2; mt++)
        #pragma unroll
        for (int nt = 0; nt < 4; nt++)
            #pragma unroll
            for (int i = 0; i < 4; i++) c[mt][nt][i] = 0.f;

    float4 ra[4], rb[2];

    // prologue: load chunk 0
    #pragma unroll
    for (int it = 0; it < 4; it++) {
        int grow = row0 + ar + 32 * it;
        ra[it] = make_float4(0.f, 0.f, 0.f, 0.f);
        if (grow < N_NODES)
            ra[it] = *(const float4*)&X[(size_t)grow * CH + ac4 * 4];
    }
    #pragma unroll
    for (int it = 0; it < 2; it++)
        rb[it] = *(const float4*)&W[(size_t)(bk + 16 * it) * WS + col0 + bc4 * 4];

    int buf = 0;
    for (int cch = 0; cch < 8; cch++) {
        unsigned* sA = smu + buf * GBUF_F;
        unsigned* sB = sA + 128 * 36;
        // stage (cvt once)
        #pragma unroll
        for (int it = 0; it < 4; it++)
            ((uint4*)sA)[(ar + 32 * it) * 9 + ac4] = f2tf4(ra[it]);
        #pragma unroll
        for (int it = 0; it < 2; it++)
            ((uint4*)sB)[(bk + 16 * it) * 18 + bc4] = f2tf4(rb[it]);
        __syncthreads();

        // prefetch next chunk into regs (overlaps with compute below)
        if (cch < 7) {
            int k0 = (cch + 1) * 32;
            #pragma unroll
            for (int it = 0; it < 4; it++) {
                int grow = row0 + ar + 32 * it;
                ra[it] = make_float4(0.f, 0.f, 0.f, 0.f);
                if (grow < N_NODES)
                    ra[it] = *(const float4*)&X[(size_t)grow * CH + k0 + ac4 * 4];
            }
            #pragma unroll
            for (int it = 0; it < 2; it++)
                rb[it] = *(const float4*)&W[(size_t)(k0 + bk + 16 * it) * WS + col0 + bc4 * 4];
        }

        // compute from smem (pure LDS + HMMA)
        #pragma unroll
        for (int k8 = 0; k8 < 4; k8++) {
            int kc = k8 * 8 + lc;
            unsigned a[2][4];
            #pragma unroll
            for (int mt = 0; mt < 2; mt++) {
                int r = warp_m * 32 + mt * 16 + lr;
                a[mt][0] = sA[r * 36 + kc];
                a[mt][1] = sA[(r + 8) * 36 + kc];
                a[mt][2] = sA[r * 36 + kc + 4];
                a[mt][3] = sA[(r + 8) * 36 + kc + 4];
            }
            #pragma unroll
            for (int nt = 0; nt < 4; nt++) {
                int cb = warp_n * 32 + nt * 8 + lr;
                unsigned b0 = sB[kc * 72 + cb];
                unsigned b1 = sB[(kc + 4) * 72 + cb];
                mma_tf32(c[0][nt], a[0], b0, b1);
                mma_tf32(c[1][nt], a[1], b0, b1);
            }
        }
        buf ^= 1;
    }

    #pragma unroll
    for (int mt = 0; mt < 2; mt++) {
        int r0 = row0 + warp_m * 32 + mt * 16 + lr;
        #pragma unroll
        for (int nt = 0; nt < 4; nt++) {
            int cc = col0 + warp_n * 32 + nt * 8 + 2 * lc;
            if (r0 < N_NODES)
                *(float2*)&OUT[(size_t)r0 * WS + cc] = make_float2(c[mt][nt][0], c[mt][nt][1]);
            if (r0 + 8 < N_NODES)
                *(float2*)&OUT[(size_t)(r0 + 8) * WS + cc] = make_float2(c[mt][nt][2], c[mt][nt][3]);
        }
    }
}

// ---------------------------------------------------------------------------
// CSR build: histogram -> 3-pass exclusive scan -> bucket fill
// ---------------------------------------------------------------------------
__global__ void zero_cnt() {
    int i = blockIdx.x * blockDim.x + threadIdx.x;
    if (i < N_NODES) g_cnt[i] = 0;
}

__global__ void hist(const int* __restrict__ ei) {
    int e = blockIdx.x * blockDim.x + threadIdx.x;
    if (e >= N_EDGES) return;
    int d = ei[N_EDGES + e];
    if ((unsigned)d < N_NODES) atomicAdd(&g_cnt[d], 1);
}

__global__ void __launch_bounds__(SCAN_CHUNK) scan1() {
    __shared__ int s[SCAN_CHUNK];
    int tid = threadIdx.x;
    int i = blockIdx.x * SCAN_CHUNK + tid;
    s[tid] = (i < N_NODES) ? g_cnt[i] : 0;
    __syncthreads();
    #pragma unroll
    for (int off = SCAN_CHUNK / 2; off > 0; off >>= 1) {
        if (tid < off) s[tid] += s[tid + off];
        __syncthreads();
    }
    if (tid == 0) g_partial[blockIdx.x] = s[0];
}

__global__ void __launch_bounds__(256) scan2() {
    __shared__ int s[256];
    int tid = threadIdx.x;
    int v = (tid < NBLK_SCAN) ? g_partial[tid] : 0;
    s[tid] = v;
    __syncthreads();
    #pragma unroll
    for (int off = 1; off < 256; off <<= 1) {
        int t = (tid >= off) ? s[tid - off] : 0;
        __syncthreads();
        s[tid] += t;
        __syncthreads();
    }
    if (tid < NBLK_SCAN) g_poff[tid] = s[tid] - v;
    if (tid == NBLK_SCAN - 1) g_rowptr[N_NODES] = s[tid];
}

__global__ void __launch_bounds__(SCAN_CHUNK) scan3() {
    __shared__ int s[SCAN_CHUNK];
    int tid = threadIdx.x;
    int i = blockIdx.x * SCAN_CHUNK + tid;
    int c = (i < N_NODES) ? g_cnt[i] : 0;
    s[tid] = c;
    __syncthreads();
    #pragma unroll
    for (int off = 1; off < SCAN_CHUNK; off <<= 1) {
        int t = (tid >= off) ? s[tid - off] : 0;
        __syncthreads();
        s[tid] += t;
        __syncthreads();
    }
    if (i < N_NODES) {
        int excl = g_poff[blockIdx.x] + s[tid] - c;
        g_rowptr[i] = excl;
        g_cursor[i] = excl;
        g_dis[i] = rsqrtf((float)(c + 1));
    }
}

__global__ void fill(const int* __restrict__ ei) {
    int e = blockIdx.x * blockDim.x + threadIdx.x;
    if (e >= N_EDGES) return;
    int src = ei[e];
    int dst = ei[N_EDGES + e];
    if ((unsigned)src >= N_NODES || (unsigned)dst >= N_NODES) return;
    int p = atomicAdd(&g_cursor[dst], 1);
    g_csrc[p] = src;
}

// ---------------------------------------------------------------------------
// Gather: warp per node. h[i] = b + dis[i]*(dis[i]*xw[i] + sum dis[s]*xw[s])
// ---------------------------------------------------------------------------
__global__ void __launch_bounds__(256) gather(const float* __restrict__ b_gcn) {
    int node = blockIdx.x * 8 + (threadIdx.x >> 5);
    if (node >= N_NODES) return;
    int lane = threadIdx.x & 31;
    const float4* xw4 = (const float4*)g_xw;
    const float4* b4  = (const float4*)b_gcn;

    float di = g_dis[node];
    float4 v0 = xw4[(size_t)node * 64 + lane];
    float4 v1 = xw4[(size_t)node * 64 + 32 + lane];
    float4 acc0 = make_float4(di * v0.x, di * v0.y, di * v0.z, di * v0.w);
    float4 acc1 = make_float4(di * v1.x, di * v1.y, di * v1.z, di * v1.w);

    int beg = g_rowptr[node], end = g_rowptr[node + 1];
    for (int j = beg; j < end; j++) {
        int s = g_csrc[j];
        float cc = g_dis[s];
        float4 w0 = xw4[(size_t)s * 64 + lane];
        float4 w1 = xw4[(size_t)s * 64 + 32 + lane];
        acc0.x += cc * w0.x; acc0.y += cc * w0.y;
        acc0.z += cc * w0.z; acc0.w += cc * w0.w;
        acc1.x += cc * w1.x; acc1.y += cc * w1.y;
        acc1.z += cc * w1.z; acc1.w += cc * w1.w;
    }

    float4 bv0 = b4[lane], bv1 = b4[lane + 32];
    float4* h4 = (float4*)g_h;
    h4[(size_t)node * 64 + lane] =
        make_float4(bv0.x + di * acc0.x, bv0.y + di * acc0.y,
                    bv0.z + di * acc0.z, bv0.w + di * acc0.w);
    h4[(size_t)node * 64 + 32 + lane] =
        make_float4(bv1.x + di * acc1.x, bv1.y + di * acc1.y,
                    bv1.z + di * acc1.z, bv1.w + di * acc1.w);
}

// ---------------------------------------------------------------------------
// Edge MLP (unchanged from round-9 PASS): 128 edges/block, layer-2 on mma.
// ---------------------------------------------------------------------------
#define TE2       128
#define SO2_STR   132
#define SW2_STR   40
#define MLP2_SMEM_W (TE2 * SO2_STR + H1 * SW2_STR)
#define MLP2_SMEM_B (MLP2_SMEM_W * 4)

__global__ void __launch_bounds__(256)
mlp2_kernel(const int* __restrict__ eli,
            const float* __restrict__ b1, const float* __restrict__ W2,
            const float* __restrict__ b2, const float* __restrict__ W3,
            const float* __restrict__ b3, float* __restrict__ out) {
    extern __shared__ __align__(16) unsigned smu[];
    __shared__ int sIdx[2 * TE2];

    unsigned* sO  = smu;
    unsigned* sW2 = smu + TE2 * SO2_STR;

    const int tid  = threadIdx.x;
    const int lane = tid & 31, warp = tid >> 5;
    const int lr = lane >> 2, lc = lane & 3;
    const int tile0 = blockIdx.x * TE2;

    if (tid < TE2) {
        int v = eli[tile0 + tid];
        sIdx[tid] = ((unsigned)v < N_NODES) ? v : 0;
    } else {
        int v = eli[N_LABEL + tile0 + tid - TE2];
        sIdx[tid] = ((unsigned)v < N_NODES) ? v : 0;
    }
    __syncthreads();

    const float4* z4  = (const float4*)g_z;
    const float4* b14 = (const float4*)b1;
    #pragma unroll
    for (int it = 0; it < 16; it++) {
        int idx = tid + 256 * it;
        int e = idx >> 5, c4 = idx & 31;
        int a = sIdx[e], b = sIdx[TE2 + e];
        float4 va = z4[(size_t)a * 32 + c4];
        float4 vb = z4[(size_t)b * 32 + c4];
        float4 bi = b14[c4];
        ((uint4*)sO)[e * 33 + c4] = make_uint4(
            f2tf(fmaxf(vb.x - va.x + bi.x, 0.f)),
            f2tf(fmaxf(vb.y - va.y + bi.y, 0.f)),
            f2tf(fmaxf(vb.z - va.z + bi.z, 0.f)),
            f2tf(fmaxf(vb.w - va.w + bi.w, 0.f)));
    }
    #pragma unroll
    for (int it = 0; it < 16; it++) {
        int idx = tid + 256 * it;
        int k = idx >> 5, n = idx & 31;
        sW2[k * SW2_STR + n] = f2tf(W2[idx]);
    }
    __syncthreads();

    float c[4][4];
    #pragma unroll
    for (int nt = 0; nt < 4; nt++)
        #pragma unroll
        for (int i = 0; i < 4; i++) c[nt][i] = 0.f;

    #pragma unroll
    for (int k8 = 0; k8 < 16; k8++) {
        int kc = k8 * 8 + lc;
        int r = warp * 16 + lr;
        unsigned a[4];
        a[0] = sO[r * SO2_STR + kc];
        a[1] = sO[(r + 8) * SO2_STR + kc];
        a[2] = sO[r * SO2_STR + kc + 4];
        a[3] = sO[(r + 8) * SO2_STR + kc + 4];
        #pragma unroll
        for (int nt = 0; nt < 4; nt++) {
            int cb = nt * 8 + lr;
            unsigned b0 = sW2[kc * SW2_STR + cb];
            unsigned b1v = sW2[(kc + 4) * SW2_STR + cb];
            mma_tf32(c[nt], a, b0, b1v);
        }
    }

    const float b3r = b3[0];
    float p0 = 0.f, p1 = 0.f;
    #pragma unroll
    for (int nt = 0; nt < 4; nt++) {
        int n0 = nt * 8 + 2 * lc;
        float b20 = b2[n0], b21 = b2[n0 + 1];
        float w30 = W3[n0], w31 = W3[n0 + 1];
        p0 += fmaxf(c[nt][0] + b20, 0.f) * w30 + fmaxf(c[nt][1] + b21, 0.f) * w31;
        p1 += fmaxf(c[nt][2] + b20, 0.f) * w30 + fmaxf(c[nt][3] + b21, 0.f) * w31;
    }
    p0 += __shfl_xor_sync(0xffffffffu, p0, 1);
    p0 += __shfl_xor_sync(0xffffffffu, p0, 2);
    p1 += __shfl_xor_sync(0xffffffffu, p1, 1);
    p1 += __shfl_xor_sync(0xffffffffu, p1, 2);
    if (lc == 0) {
        int r = tile0 + warp * 16 + lr;
        out[r] = p0 + b3r;
        out[r + 8] = p1 + b3r;
    }
}

// ---------------------------------------------------------------------------
// Host: resolve inputs BY ELEMENT COUNT; gemm_tf32<256> is launch #4.
// ---------------------------------------------------------------------------
extern "C" void kernel_launch(void* const* d_in, const int* in_sizes, int n_in,
                              void* d_out, int out_size) {
    const float *x = 0, *W_gcn = 0, *b_gcn = 0, *W1 = 0, *b1 = 0, *W2 = 0,
                *b2 = 0, *W3 = 0, *b3 = 0;
    const int *ei = 0, *eli = 0;
    int idx32[2] = {-1, -1};
    int n32 = 0, i128 = -1;

    for (int i = 0; i < n_in; i++) {
        switch (in_sizes[i]) {
            case 25600000: x     = (const float*)d_in[i]; break;
            case 1600000:  ei    = (const int*)d_in[i];   break;
            case 800000:   eli   = (const int*)d_in[i];   break;
            case 65536:    W_gcn = (const float*)d_in[i]; break;
            case 32768:    W1    = (const float*)d_in[i]; break;
            case 4096:     W2    = (const float*)d_in[i]; break;
            case 256:      b_gcn = (const float*)d_in[i]; break;
            case 128:      b1    = (const float*)d_in[i]; i128 = i; break;
            case 32:       if (n32 < 2) idx32[n32] = i; n32++; break;
            case 1:        b3    = (const float*)d_in[i]; break;
            default: break;
        }
    }
    if (n32 >= 2) {
        if (idx32[0] < i128) {
            W3 = (const float*)d_in[idx32[0]];
            b2 = (const float*)d_in[idx32[1]];
        } else {
            b2 = (const float*)d_in[idx32[0]];
            W3 = (const float*)d_in[idx32[1]];
        }
    }
    if (!x)     x     = (const float*)d_in[0];
    if (!ei)    ei    = (const int*)d_in[1];
    if (!eli)   eli   = (const int*)d_in[2];
    if (!W_gcn) W_gcn = (const float*)d_in[3];
    if (!b_gcn) b_gcn = (const float*)d_in[4];
    if (!W1)    W1    = (const float*)d_in[5];
    if (!b1)    b1    = (const float*)d_in[6];
    if (!W2)    W2    = (const float*)d_in[7];
    if (!b2)    b2    = (const float*)d_in[8];
    if (!W3)    W3    = (const float*)d_in[9];
    if (!b3)    b3    = (const float*)d_in[10];
    float* out = (float*)d_out;

    cudaFuncSetAttribute(gemm_tf32<CH>, cudaFuncAttributeMaxDynamicSharedMemorySize,
                         GSMEM_B);
    cudaFuncSetAttribute(gemm_tf32<H1>, cudaFuncAttributeMaxDynamicSharedMemorySize,
                         GSMEM_B);
    cudaFuncSetAttribute(mlp2_kernel, cudaFuncAttributeMaxDynamicSharedMemorySize,
                         MLP2_SMEM_B);

    float* xw = 0;
    cudaGetSymbolAddress((void**)&xw, g_xw);
    float* h = 0;
    cudaGetSymbolAddress((void**)&h, g_h);
    float* z = 0;
    cudaGetSymbolAddress((void**)&z, g_z);

    zero_cnt<<<(N_NODES + 255) / 256, 256>>>();
    hist<<<(N_EDGES + 255) / 256, 256>>>(ei);
    scan1<<<NBLK_SCAN, SCAN_CHUNK>>>();

    // launch #4 (ncu window): xw = x @ W_gcn
    dim3 g1(CH / 64, (N_NODES + 127) / 128);
    gemm_tf32<CH><<<g1, 256, GSMEM_B>>>(x, W_gcn, xw);

    scan2<<<1, 256>>>();
    scan3<<<NBLK_SCAN, SCAN_CHUNK>>>();
    fill<<<(N_EDGES + 255) / 256, 256>>>(ei);
    gather<<<(N_NODES + 7) / 8, 256>>>(b_gcn);

    // Z = h @ W1
    dim3 g2(H1 / 64, (N_NODES + 127) / 128);
    gemm_tf32<H1><<<g2, 256, GSMEM_B>>>(h, W1, z);

    mlp2_kernel<<<N_LABEL / TE2, 256, MLP2_SMEM_B>>>(eli, b1, W2, b2, W3, b3, out);
}

// round 11
// speedup vs baseline: 8.2677x; 1.2186x over previous
#include <cuda_runtime.h>

#define N_NODES 100000
#define N_EDGES 800000
#define N_LABEL 400000
#define CH      256
#define H1      128
#define H2      32

#define SCAN_CHUNK 512
#define NBLK_SCAN  ((N_NODES + SCAN_CHUNK - 1) / SCAN_CHUNK)   // 196

// Scratch (module-load allocated; allowed per harness rules)
__device__ __align__(16) float g_xw[(size_t)N_NODES * CH];
__device__ __align__(16) float g_y[(size_t)N_NODES * H1];
__device__ __align__(16) float g_z[(size_t)N_NODES * H1];
__device__ float g_dis[N_NODES];
__device__ int   g_cnt[N_NODES];
__device__ int   g_rowptr[N_NODES + 1];
__device__ int   g_cursor[N_NODES];
__device__ int   g_csrc[N_EDGES];
__device__ int   g_partial[NBLK_SCAN];
__device__ int   g_poff[NBLK_SCAN];

// ---------------------------------------------------------------------------
// tf32 mma helpers (m16n8k8, row.col, fp32 accumulate)
// ---------------------------------------------------------------------------
__device__ __forceinline__ unsigned f2tf(float f) {
    unsigned r;
    asm("cvt.rna.tf32.f32 %0, %1;" : "=r"(r) : "f"(f));
    return r;
}

__device__ __forceinline__ uint4 f2tf4(float4 v) {
    return make_uint4(f2tf(v.x), f2tf(v.y), f2tf(v.z), f2tf(v.w));
}

__device__ __forceinline__ void mma_tf32(float* c, const unsigned* a,
                                         unsigned b0, unsigned b1) {
    asm("mma.sync.aligned.m16n8k8.row.col.f32.tf32.tf32.f32 "
        "{%0,%1,%2,%3},{%4,%5,%6,%7},{%8,%9},{%0,%1,%2,%3};"
        : "+f"(c[0]), "+f"(c[1]), "+f"(c[2]), "+f"(c[3])
        : "r"(a[0]), "r"(a[1]), "r"(a[2]), "r"(a[3]), "r"(b0), "r"(b1));
}

// ---------------------------------------------------------------------------
// Pipelined tf32 GEMM, smem-BW-optimized: OUT[Nx ND] = X[Nx256] @ W[256 x ND].
// Block tile 128M x 128N, 8 warps (4m x 2n), warp tile 32x64 (192 B/HMMA).
// k-chunks of 32, double-buffered smem, reg prefetch, 1 sync per chunk.
// sA stride 36 fl (banks 4*lr+lc), sB stride 136 fl (banks 8*lc+lr): clean.
// ---------------------------------------------------------------------------
#define GA_F     (128 * 36)
#define GB_F     (32 * 136)
#define GBUF2_F  (GA_F + GB_F)                 // 8960 words per buffer
#define GSMEM2_B (2 * GBUF2_F * 4)             // 71680 bytes

template<int ND>
__global__ void __launch_bounds__(256)
gemm_tf32(const float* __restrict__ X, const float* __restrict__ W,
          float* __restrict__ OUT) {
    extern __shared__ __align__(16) unsigned smu[];
    const int tid = threadIdx.x;
    const int lane = tid & 31, warp = tid >> 5;
    const int warp_m = warp >> 1, warp_n = warp & 1;
    const int row0 = blockIdx.y * 128, col0 = blockIdx.x * 128;
    const int lr = lane >> 2, lc = lane & 3;

    // staging coordinates: A 1024 f4 (r=idx>>3, c4=idx&7), B 1024 f4 (k=idx>>5, c4=idx&31)
    const int ar = tid >> 3, ac4 = tid & 7;
    const int bk = tid >> 5, bc4 = tid & 31;

    float c[2][8][4];
    #pragma unroll
    for (int mt = 0; mt < 2; mt++)
        #pragma unroll
        for (int nt = 0; nt < 8; nt++)
            #pragma unroll
            for (int i = 0; i < 4; i++) c[mt][nt][i] = 0.f;

    float4 ra[4], rb[4];

    // prologue: chunk 0
    #pragma unroll
    for (int it = 0; it < 4; it++) {
        int grow = row0 + ar + 32 * it;
        ra[it] = make_float4(0.f, 0.f, 0.f, 0.f);
        if (grow < N_NODES)
            ra[it] = *(const float4*)&X[(size_t)grow * CH + ac4 * 4];
    }
    #pragma unroll
    for (int it = 0; it < 4; it++)
        rb[it] = *(const float4*)&W[(size_t)(bk + 8 * it) * ND + col0 + bc4 * 4];

    int buf = 0;
    for (int cch = 0; cch < 8; cch++) {
        unsigned* sA = smu + buf * GBUF2_F;
        unsigned* sB = sA + GA_F;
        #pragma unroll
        for (int it = 0; it < 4; it++)
            ((uint4*)sA)[(ar + 32 * it) * 9 + ac4] = f2tf4(ra[it]);
        #pragma unroll
        for (int it = 0; it < 4; it++)
            ((uint4*)sB)[(bk + 8 * it) * 34 + bc4] = f2tf4(rb[it]);
        __syncthreads();

        if (cch < 7) {
            int k0 = (cch + 1) * 32;
            #pragma unroll
            for (int it = 0; it < 4; it++) {
                int grow = row0 + ar + 32 * it;
                ra[it] = make_float4(0.f, 0.f, 0.f, 0.f);
                if (grow < N_NODES)
                    ra[it] = *(const float4*)&X[(size_t)grow * CH + k0 + ac4 * 4];
            }
            #pragma unroll
            for (int it = 0; it < 4; it++)
                rb[it] = *(const float4*)&W[(size_t)(k0 + bk + 8 * it) * ND + col0 + bc4 * 4];
        }

        #pragma unroll
        for (int k8 = 0; k8 < 4; k8++) {
            int kc = k8 * 8 + lc;
            unsigned a[2][4];
            #pragma unroll
            for (int mt = 0; mt < 2; mt++) {
                int r = warp_m * 32 + mt * 16 + lr;
                a[mt][0] = sA[r * 36 + kc];
                a[mt][1] = sA[(r + 8) * 36 + kc];
                a[mt][2] = sA[r * 36 + kc + 4];
                a[mt][3] = sA[(r + 8) * 36 + kc + 4];
            }
            #pragma unroll
            for (int nt = 0; nt < 8; nt++) {
                int cb = warp_n * 64 + nt * 8 + lr;
                unsigned b0 = sB[kc * 136 + cb];
                unsigned b1 = sB[(kc + 4) * 136 + cb];
                mma_tf32(c[0][nt], a[0], b0, b1);
                mma_tf32(c[1][nt], a[1], b0, b1);
            }
        }
        buf ^= 1;
    }

    #pragma unroll
    for (int mt = 0; mt < 2; mt++) {
        int r0 = row0 + warp_m * 32 + mt * 16 + lr;
        #pragma unroll
        for (int nt = 0; nt < 8; nt++) {
            int cc = col0 + warp_n * 64 + nt * 8 + 2 * lc;
            if (r0 < N_NODES)
                *(float2*)&OUT[(size_t)r0 * ND + cc] = make_float2(c[mt][nt][0], c[mt][nt][1]);
            if (r0 + 8 < N_NODES)
                *(float2*)&OUT[(size_t)(r0 + 8) * ND + cc] = make_float2(c[mt][nt][2], c[mt][nt][3]);
        }
    }
}

// ---------------------------------------------------------------------------
// CSR build: histogram -> 3-pass exclusive scan -> bucket fill
// ---------------------------------------------------------------------------
__global__ void zero_cnt() {
    int i = blockIdx.x * blockDim.x + threadIdx.x;
    if (i < N_NODES) g_cnt[i] = 0;
}

__global__ void hist(const int* __restrict__ ei) {
    int e = blockIdx.x * blockDim.x + threadIdx.x;
    if (e >= N_EDGES) return;
    int d = ei[N_EDGES + e];
    if ((unsigned)d < N_NODES) atomicAdd(&g_cnt[d], 1);
}

__global__ void __launch_bounds__(SCAN_CHUNK) scan1() {
    __shared__ int s[SCAN_CHUNK];
    int tid = threadIdx.x;
    int i = blockIdx.x * SCAN_CHUNK + tid;
    s[tid] = (i < N_NODES) ? g_cnt[i] : 0;
    __syncthreads();
    #pragma unroll
    for (int off = SCAN_CHUNK / 2; off > 0; off >>= 1) {
        if (tid < off) s[tid] += s[tid + off];
        __syncthreads();
    }
    if (tid == 0) g_partial[blockIdx.x] = s[0];
}

__global__ void __launch_bounds__(256) scan2() {
    __shared__ int s[256];
    int tid = threadIdx.x;
    int v = (tid < NBLK_SCAN) ? g_partial[tid] : 0;
    s[tid] = v;
    __syncthreads();
    #pragma unroll
    for (int off = 1; off < 256; off <<= 1) {
        int t = (tid >= off) ? s[tid - off] : 0;
        __syncthreads();
        s[tid] += t;
        __syncthreads();
    }
    if (tid < NBLK_SCAN) g_poff[tid] = s[tid] - v;
    if (tid == NBLK_SCAN - 1) g_rowptr[N_NODES] = s[tid];
}

__global__ void __launch_bounds__(SCAN_CHUNK) scan3() {
    __shared__ int s[SCAN_CHUNK];
    int tid = threadIdx.x;
    int i = blockIdx.x * SCAN_CHUNK + tid;
    int c = (i < N_NODES) ? g_cnt[i] : 0;
    s[tid] = c;
    __syncthreads();
    #pragma unroll
    for (int off = 1; off < SCAN_CHUNK; off <<= 1) {
        int t = (tid >= off) ? s[tid - off] : 0;
        __syncthreads();
        s[tid] += t;
        __syncthreads();
    }
    if (i < N_NODES) {
        int excl = g_poff[blockIdx.x] + s[tid] - c;
        g_rowptr[i] = excl;
        g_cursor[i] = excl;
        g_dis[i] = rsqrtf((float)(c + 1));
    }
}

__global__ void fill(const int* __restrict__ ei) {
    int e = blockIdx.x * blockDim.x + threadIdx.x;
    if (e >= N_EDGES) return;
    int src = ei[e];
    int dst = ei[N_EDGES + e];
    if ((unsigned)src >= N_NODES || (unsigned)dst >= N_NODES) return;
    int p = atomicAdd(&g_cursor[dst], 1);
    g_csrc[p] = src;
}

// ---------------------------------------------------------------------------
// Gather on y (128-wide): z[i] = dis_i*(dis_i*y[i] + sum_{s in in(i)} dis_s*y[s])
// (b_gcn@W1 term cancels in the edge difference, so it is omitted.)
// Warp per node; lane owns exactly one float4 of the 128-wide row.
// ---------------------------------------------------------------------------
__global__ void __launch_bounds__(256) gather128() {
    int node = blockIdx.x * 8 + (threadIdx.x >> 5);
    if (node >= N_NODES) return;
    int lane = threadIdx.x & 31;
    const float4* y4 = (const float4*)g_y;

    float di = g_dis[node];
    float4 v = y4[(size_t)node * 32 + lane];
    float4 acc = make_float4(di * v.x, di * v.y, di * v.z, di * v.w);

    int beg = g_rowptr[node], end = g_rowptr[node + 1];
    for (int j = beg; j < end; j++) {
        int s = g_csrc[j];
        float cc = g_dis[s];
        float4 w = y4[(size_t)s * 32 + lane];
        acc.x += cc * w.x; acc.y += cc * w.y;
        acc.z += cc * w.z; acc.w += cc * w.w;
    }

    ((float4*)g_z)[(size_t)node * 32 + lane] =
        make_float4(di * acc.x, di * acc.y, di * acc.z, di * acc.w);
}

// ---------------------------------------------------------------------------
// Edge MLP (unchanged from round-9/10 PASS): 128 edges/block, layer-2 on mma.
// ---------------------------------------------------------------------------
#define TE2       128
#define SO2_STR   132
#define SW2_STR   40
#define MLP2_SMEM_W (TE2 * SO2_STR + H1 * SW2_STR)
#define MLP2_SMEM_B (MLP2_SMEM_W * 4)

__global__ void __launch_bounds__(256)
mlp2_kernel(const int* __restrict__ eli,
            const float* __restrict__ b1, const float* __restrict__ W2,
            const float* __restrict__ b2, const float* __restrict__ W3,
            const float* __restrict__ b3, float* __restrict__ out) {
    extern __shared__ __align__(16) unsigned smu[];
    __shared__ int sIdx[2 * TE2];

    unsigned* sO  = smu;
    unsigned* sW2 = smu + TE2 * SO2_STR;

    const int tid  = threadIdx.x;
    const int lane = tid & 31, warp = tid >> 5;
    const int lr = lane >> 2, lc = lane & 3;
    const int tile0 = blockIdx.x * TE2;

    if (tid < TE2) {
        int v = eli[tile0 + tid];
        sIdx[tid] = ((unsigned)v < N_NODES) ? v : 0;
    } else {
        int v = eli[N_LABEL + tile0 + tid - TE2];
        sIdx[tid] = ((unsigned)v < N_NODES) ? v : 0;
    }
    __syncthreads();

    const float4* z4  = (const float4*)g_z;
    const float4* b14 = (const float4*)b1;
    #pragma unroll
    for (int it = 0; it < 16; it++) {
        int idx = tid + 256 * it;
        int e = idx >> 5, c4 = idx & 31;
        int a = sIdx[e], b = sIdx[TE2 + e];
        float4 va = z4[(size_t)a * 32 + c4];
        float4 vb = z4[(size_t)b * 32 + c4];
        float4 bi = b14[c4];
        ((uint4*)sO)[e * 33 + c4] = make_uint4(
            f2tf(fmaxf(vb.x - va.x + bi.x, 0.f)),
            f2tf(fmaxf(vb.y - va.y + bi.y, 0.f)),
            f2tf(fmaxf(vb.z - va.z + bi.z, 0.f)),
            f2tf(fmaxf(vb.w - va.w + bi.w, 0.f)));
    }
    #pragma unroll
    for (int it = 0; it < 16; it++) {
        int idx = tid + 256 * it;
        int k = idx >> 5, n = idx & 31;
        sW2[k * SW2_STR + n] = f2tf(W2[idx]);
    }
    __syncthreads();

    float c[4][4];
    #pragma unroll
    for (int nt = 0; nt < 4; nt++)
        #pragma unroll
        for (int i = 0; i < 4; i++) c[nt][i] = 0.f;

    #pragma unroll
    for (int k8 = 0; k8 < 16; k8++) {
        int kc = k8 * 8 + lc;
        int r = warp * 16 + lr;
        unsigned a[4];
        a[0] = sO[r * SO2_STR + kc];
        a[1] = sO[(r + 8) * SO2_STR + kc];
        a[2] = sO[r * SO2_STR + kc + 4];
        a[3] = sO[(r + 8) * SO2_STR + kc + 4];
        #pragma unroll
        for (int nt = 0; nt < 4; nt++) {
            int cb = nt * 8 + lr;
            unsigned b0 = sW2[kc * SW2_STR + cb];
            unsigned b1v = sW2[(kc + 4) * SW2_STR + cb];
            mma_tf32(c[nt], a, b0, b1v);
        }
    }

    const float b3r = b3[0];
    float p0 = 0.f, p1 = 0.f;
    #pragma unroll
    for (int nt = 0; nt < 4; nt++) {
        int n0 = nt * 8 + 2 * lc;
        float b20 = b2[n0], b21 = b2[n0 + 1];
        float w30 = W3[n0], w31 = W3[n0 + 1];
        p0 += fmaxf(c[nt][0] + b20, 0.f) * w30 + fmaxf(c[nt][1] + b21, 0.f) * w31;
        p1 += fmaxf(c[nt][2] + b20, 0.f) * w30 + fmaxf(c[nt][3] + b21, 0.f) * w31;
    }
    p0 += __shfl_xor_sync(0xffffffffu, p0, 1);
    p0 += __shfl_xor_sync(0xffffffffu, p0, 2);
    p1 += __shfl_xor_sync(0xffffffffu, p1, 1);
    p1 += __shfl_xor_sync(0xffffffffu, p1, 2);
    if (lc == 0) {
        int r = tile0 + warp * 16 + lr;
        out[r] = p0 + b3r;
        out[r + 8] = p1 + b3r;
    }
}

// ---------------------------------------------------------------------------
// Host: resolve inputs BY ELEMENT COUNT; gemm_tf32<256> is launch #4.
// ---------------------------------------------------------------------------
extern "C" void kernel_launch(void* const* d_in, const int* in_sizes, int n_in,
                              void* d_out, int out_size) {
    const float *x = 0, *W_gcn = 0, *b_gcn = 0, *W1 = 0, *b1 = 0, *W2 = 0,
                *b2 = 0, *W3 = 0, *b3 = 0;
    const int *ei = 0, *eli = 0;
    int idx32[2] = {-1, -1};
    int n32 = 0, i128 = -1;

    for (int i = 0; i < n_in; i++) {
        switch (in_sizes[i]) {
            case 25600000: x     = (const float*)d_in[i]; break;
            case 1600000:  ei    = (const int*)d_in[i];   break;
            case 800000:   eli   = (const int*)d_in[i];   break;
            case 65536:    W_gcn = (const float*)d_in[i]; break;
            case 32768:    W1    = (const float*)d_in[i]; break;
            case 4096:     W2    = (const float*)d_in[i]; break;
            case 256:      b_gcn = (const float*)d_in[i]; break;
            case 128:      b1    = (const float*)d_in[i]; i128 = i; break;
            case 32:       if (n32 < 2) idx32[n32] = i; n32++; break;
            case 1:        b3    = (const float*)d_in[i]; break;
            default: break;
        }
    }
    if (n32 >= 2) {
        if (idx32[0] < i128) {
            W3 = (const float*)d_in[idx32[0]];
            b2 = (const float*)d_in[idx32[1]];
        } else {
            b2 = (const float*)d_in[idx32[0]];
            W3 = (const float*)d_in[idx32[1]];
        }
    }
    if (!x)     x     = (const float*)d_in[0];
    if (!ei)    ei    = (const int*)d_in[1];
    if (!eli)   eli   = (const int*)d_in[2];
    if (!W_gcn) W_gcn = (const float*)d_in[3];
    if (!b_gcn) b_gcn = (const float*)d_in[4];
    if (!W1)    W1    = (const float*)d_in[5];
    if (!b1)    b1    = (const float*)d_in[6];
    if (!W2)    W2    = (const float*)d_in[7];
    if (!b2)    b2    = (const float*)d_in[8];
    if (!W3)    W3    = (const float*)d_in[9];
    if (!b3)    b3    = (const float*)d_in[10];
    float* out = (float*)d_out;

    cudaFuncSetAttribute(gemm_tf32<CH>, cudaFuncAttributeMaxDynamicSharedMemorySize,
                         GSMEM2_B);
    cudaFuncSetAttribute(gemm_tf32<H1>, cudaFuncAttributeMaxDynamicSharedMemorySize,
                         GSMEM2_B);
    cudaFuncSetAttribute(mlp2_kernel, cudaFuncAttributeMaxDynamicSharedMemorySize,
                         MLP2_SMEM_B);

    float* xw = 0;
    cudaGetSymbolAddress((void**)&xw, g_xw);
    float* y = 0;
    cudaGetSymbolAddress((void**)&y, g_y);

    zero_cnt<<<(N_NODES + 255) / 256, 256>>>();
    hist<<<(N_EDGES + 255) / 256, 256>>>(ei);
    scan1<<<NBLK_SCAN, SCAN_CHUNK>>>();

    // launch #4 (ncu window): xw = x @ W_gcn   (block tile 128x128)
    dim3 g1(CH / 128, (N_NODES + 127) / 128);
    gemm_tf32<CH><<<g1, 256, GSMEM2_B>>>(x, W_gcn, xw);

    scan2<<<1, 256>>>();
    scan3<<<NBLK_SCAN, SCAN_CHUNK>>>();
    fill<<<(N_EDGES + 255) / 256, 256>>>(ei);

    // y = xw @ W1  (dense, BEFORE the sparse aggregation; linearity)
    dim3 g2(H1 / 128, (N_NODES + 127) / 128);
    gemm_tf32<H1><<<g2, 256, GSMEM2_B>>>(xw, W1, y);

    gather128<<<(N_NODES + 7) / 8, 256>>>();

    mlp2_kernel<<<N_LABEL / TE2, 256, MLP2_SMEM_B>>>(eli, b1, W2, b2, W3, b3, out);
}